// round 2
// baseline (speedup 1.0000x reference)
#include <cuda_runtime.h>
#include <cuda_bf16.h>

// Problem constants
#define BB   2
#define NN   32
#define LL   4
#define ED   64
#define HH   4
#define HD   16
#define EPSL 1e-5f
#define CELLS (BB*NN*NN)          // 2048

// ---------------- device scratch (static; no allocation) ----------------
__device__ __align__(16) float g_adj[CELLS];          // adjacency (B,N,N)
__device__ __align__(16) float g_x[CELLS*ED];         // layer activations
__device__ __align__(16) float g_h[CELLS*ED];         // linear output h
__device__ float    g_scores[BB*32];                  // accumulated scores
__device__ unsigned g_diag_key[BB*ED];                // float-max keys
__device__ unsigned g_off_key [BB*ED];
__device__ unsigned g_min_key;                        // global-min key

// monotone float<->unsigned key (for atomicMax/atomicMin on floats)
__device__ __forceinline__ unsigned fkey(float f) {
    unsigned u = __float_as_uint(f);
    return (u & 0x80000000u) ? ~u : (u | 0x80000000u);
}
__device__ __forceinline__ float funkey(unsigned k) {
    unsigned u = (k & 0x80000000u) ? (k & 0x7fffffffu) : ~k;
    return __uint_as_float(u);
}

// ---------------- K0: adjacency + resets ----------------
__global__ void k_init(const int* ei, int E) {
    __shared__ float sadj[CELLS];
    __shared__ int sflag;
    int t = threadIdx.x;                       // 256 threads
    if (t == 0) sflag = 0;
    __syncthreads();
    // dtype detect: int64 edge_index has all odd 32-bit words zero
    for (int i = t; i < 512; i += 256)
        if (ei[2*i + 1] != 0) sflag = 1;
    for (int i = t; i < CELLS; i += 256) sadj[i] = 0.f;
    __syncthreads();
    int stride = sflag ? 1 : 2;                // 1 = int32, 2 = int64 (low words)
    for (int e = t; e < E; e += 256) {
        int e0 = ei[stride*e];
        int e1 = ei[stride*E + stride*e];
        int g  = e0 >> 5;                      // batch = arange//N  ->  g = e0/N
        int ls = e0 - (g << 5);
        int ld = e1 - (g << 5);
        if (g >= 0 && g < BB && ls >= 0 && ls < NN && ld >= 0 && ld < NN)
            atomicAdd(&sadj[(g << 10) + (ls << 5) + ld], 1.f);
    }
    __syncthreads();
    if (t < BB*NN) { int b = t >> 5, n = t & 31; sadj[(b << 10) + n*33] = 2.f; }
    __syncthreads();
    for (int i = t; i < CELLS; i += 256) g_adj[i] = sadj[i];
    if (t < BB*32) g_scores[t] = 0.f;
    if (t < BB*ED) { g_diag_key[t] = 0u; g_off_key[t] = 0u; }
    if (t == 0) g_min_key = 0xFFFFFFFFu;
}

// ---------------- pooling finish (device fn; 64 threads) ----------------
__device__ void pool_finish(int layer, const float* opW, const float* opb) {
    __shared__ float pooled[BB][2*ED];
    __shared__ float sr2[2];
    int t = threadIdx.x;
    float d0 = funkey(g_diag_key[t]);
    float d1 = funkey(g_diag_key[64 + t]);
    float o0 = funkey(g_off_key[t]);
    float o1 = funkey(g_off_key[64 + t]);
    float gmin = funkey(g_min_key);
    float m = fmaxf(d0, d1);
    #pragma unroll
    for (int o = 16; o > 0; o >>= 1) m = fmaxf(m, __shfl_xor_sync(0xffffffffu, m, o));
    if ((t & 31) == 0) sr2[t >> 5] = m;
    __syncthreads();
    float gdm = fmaxf(sr2[0], sr2[1]);
    float val = fabsf(gdm - gmin);
    pooled[0][t]      = d0;
    pooled[0][64 + t] = fmaxf(o0, d0 - val);
    pooled[1][t]      = d1;
    pooled[1][64 + t] = fmaxf(o1, d1 - val);
    __syncthreads();
    int b = t >> 5, j = t & 31;
    const float* w = opW + (layer*32 + j) * 128;
    float acc = opb[layer*32 + j];
    #pragma unroll
    for (int k = 0; k < 128; k++) acc += pooled[b][k] * w[k];
    g_scores[b*32 + j] += acc;
    // reset for next layer
    g_diag_key[t] = 0u; g_diag_key[64 + t] = 0u;
    g_off_key [t] = 0u; g_off_key [64 + t] = 0u;
    if (t == 0) g_min_key = 0xFFFFFFFFu;
}

// ---------------- K1: h = x @ W^T + b  (+finisher block) ----------------
__global__ void __launch_bounds__(64) k_h(int layer,
        const float* W0, const float* b0, const float* Ws, const float* bs,
        const float* opW, const float* opb) {
    if (blockIdx.x == CELLS) {                 // finisher for previous layer
        if (layer > 0) pool_finish(layer - 1, opW, opb);
        return;
    }
    int cell = blockIdx.x;
    int f = threadIdx.x;
    float acc;
    if (layer == 0) {
        float a = g_adj[cell];
        acc = a * W0[f] + b0[f];
    } else {
        __shared__ float sx[ED];
        sx[f] = g_x[cell*ED + f];
        __syncthreads();
        const float4* W4 = (const float4*)(Ws + (layer-1)*ED*ED + f*ED);
        const float4* x4 = (const float4*)sx;
        acc = bs[(layer-1)*ED + f];
        #pragma unroll
        for (int k = 0; k < 16; k++) {
            float4 w = W4[k], xv = x4[k];
            acc += w.x*xv.x + w.y*xv.y + w.z*xv.z + w.w*xv.w;
        }
    }
    g_h[cell*ED + f] = acc;
}

// ---------------- K2: fused attention + LN + FFN + LN ----------------
__global__ void __launch_bounds__(64) k_attn(int layer,
        const float* ln_g, const float* ln_b,
        const float* fW0, const float* fb0,
        const float* fWs, const float* fbs,
        const float* fln_g, const float* fln_b) {
    const int STR = 68;                        // padded row stride (floats)
    __shared__ __align__(16) float shx[NN*STR];
    __shared__ __align__(16) float shy[NN*STR];
    __shared__ __align__(16) float sqx[NN*STR];
    __shared__ __align__(16) float sqy[NN*STR];
    __shared__ float ss[HH][33], sm[HH][33], se[HH][33];
    __shared__ __align__(16) float sxu[ED];
    __shared__ __align__(16) float sxold[ED];
    __shared__ float slg[HD], slb[HD];
    __shared__ float sred[2];

    int t = threadIdx.x;
    int cell = blockIdx.x;
    int b = cell >> 10;
    int x = (cell >> 5) & 31;
    int y = cell & 31;
    int h = t >> 4, d = t & 15;

    if (t < HD) { slg[t] = ln_g[layer*HD + t]; slb[t] = ln_b[layer*HD + t]; }

    // stage h slabs: row slab (b,x,*) and col slab (b,*,y)
    const float4* hx4 = (const float4*)(g_h + ((b*NN + x)*NN)*ED);
    for (int idx = t; idx < 512; idx += 64) {
        int a = idx >> 4, j = idx & 15;
        float4 v = hx4[a*16 + j];
        *(float4*)&shx[a*STR + j*4] = v;
    }
    for (int idx = t; idx < 512; idx += 64) {
        int a = idx >> 4, j = idx & 15;
        float4 v = *(const float4*)(g_h + ((b*NN + a)*NN + y)*ED + j*4);
        *(float4*)&shy[a*STR + j*4] = v;
    }
    if (layer == 0) { if (t == 0) sxold[0] = g_adj[cell]; }
    else sxold[t] = g_x[cell*ED + t];
    __syncthreads();

    // phase 1: q = LN(h) per (row, head), computed in smem
    for (int g = t; g < 256; g += 64) {
        int slab = g >> 7;
        int rh = g & 127;
        int row = rh >> 2, head = rh & 3;
        const float* src = slab ? shy : shx;
        float* dst = slab ? sqy : sqx;
        int base = row*STR + head*HD;
        float v[HD]; float s = 0.f;
        #pragma unroll
        for (int k = 0; k < HD; k++) { v[k] = src[base + k]; s += v[k]; }
        float mn = s * (1.f/HD);
        float sv = 0.f;
        #pragma unroll
        for (int k = 0; k < HD; k++) { float dd = v[k] - mn; sv += dd*dd; }
        float rstd = rsqrtf(sv * (1.f/HD) + EPSL);
        #pragma unroll
        for (int k = 0; k < HD; k++) dst[base + k] = (v[k] - mn)*rstd*slg[k] + slb[k];
    }
    __syncthreads();

    // phase 2: per-a stats (score dot, mean(pr), mean((pr)^2)) via 16-lane segments
    for (int a = 0; a < NN; a++) {
        float qp = sqx[a*STR + t], qr = sqy[a*STR + t];
        float p  = shx[a*STR + t], r  = shy[a*STR + t];
        float v1 = qp*qr;
        float pr = p*r;
        float v3 = pr*pr;
        #pragma unroll
        for (int o = 8; o > 0; o >>= 1) {
            v1 += __shfl_xor_sync(0xffffffffu, v1, o, 16);
            pr += __shfl_xor_sync(0xffffffffu, pr, o, 16);
            v3 += __shfl_xor_sync(0xffffffffu, v3, o, 16);
        }
        if (d == 0) {
            ss[h][a] = v1 * 0.25f;             // /sqrt(HD)
            sm[h][a] = pr * (1.f/HD);
            se[h][a] = v3 * (1.f/HD);
        }
    }
    __syncthreads();

    // phase 3: softmax over a + fused LN(xu)-weighted contraction
    float mx = -1e30f;
    #pragma unroll
    for (int a = 0; a < NN; a++) mx = fmaxf(mx, ss[h][a]);
    float sume = 0.f;
    #pragma unroll
    for (int a = 0; a < NN; a++) sume += __expf(ss[h][a] - mx);
    float inv = 1.f / sume;
    float acc = 0.f, c = 0.f;
    for (int a = 0; a < NN; a++) {
        float att = __expf(ss[h][a] - mx) * inv;
        float m  = sm[h][a];
        float var = se[h][a] - m*m;
        float rstd = rsqrtf(var + EPSL);
        float w = att * rstd;
        acc += w * shx[a*STR + t] * shy[a*STR + t];
        c   += att * m * rstd;
    }
    sxu[t] = slg[d]*(acc - c) + slb[d];
    __syncthreads();

    // phase 4: FFN on concat([x_old, xu]) then LN over ED
    float yv;
    if (layer == 0) {
        const float* fw = fW0 + t*(1+ED);
        float s = fb0[t] + fw[0]*sxold[0];
        #pragma unroll
        for (int k = 0; k < ED; k++) s += fw[1+k]*sxu[k];
        yv = s;
    } else {
        const float4* fw4 = (const float4*)(fWs + (layer-1)*ED*2*ED + t*2*ED);
        const float4* xo4 = (const float4*)sxold;
        const float4* xu4 = (const float4*)sxu;
        float s = fbs[(layer-1)*ED + t];
        #pragma unroll
        for (int k = 0; k < 16; k++) {
            float4 w = fw4[k], v = xo4[k];
            s += w.x*v.x + w.y*v.y + w.z*v.z + w.w*v.w;
        }
        #pragma unroll
        for (int k = 0; k < 16; k++) {
            float4 w = fw4[16+k], v = xu4[k];
            s += w.x*v.x + w.y*v.y + w.z*v.z + w.w*v.w;
        }
        yv = s;
    }
    float ws = yv;
    #pragma unroll
    for (int o = 16; o > 0; o >>= 1) ws += __shfl_xor_sync(0xffffffffu, ws, o);
    if ((t & 31) == 0) sred[t >> 5] = ws;
    __syncthreads();
    float mean = (sred[0] + sred[1]) * (1.f/ED);
    float dv = yv - mean;
    float ws2 = dv*dv;
    #pragma unroll
    for (int o = 16; o > 0; o >>= 1) ws2 += __shfl_xor_sync(0xffffffffu, ws2, o);
    __syncthreads();
    if ((t & 31) == 0) sred[t >> 5] = ws2;
    __syncthreads();
    float var = (sred[0] + sred[1]) * (1.f/ED);
    float xn = dv * rsqrtf(var + EPSL) * fln_g[layer*ED + t] + fln_b[layer*ED + t];
    g_x[cell*ED + t] = xn;
}

// ---------------- K3: pooling partial reductions ----------------
__global__ void __launch_bounds__(64) k_pool_reduce() {
    int bx = blockIdx.x;                       // 0..63 : (b, x)
    int b = bx >> 5, x = bx & 31;
    int f = threadIdx.x;
    const float* base = g_x + ((b*NN + x)*NN)*ED;
    float dval = base[x*ED + f];
    float om = -1e30f, mn = dval;
    for (int y = 0; y < NN; y++) {
        float v = base[y*ED + f];
        mn = fminf(mn, v);
        if (y != x) om = fmaxf(om, v);
    }
    atomicMax(&g_diag_key[b*ED + f], fkey(dval));
    atomicMax(&g_off_key [b*ED + f], fkey(om));
    float w = mn;
    #pragma unroll
    for (int o = 16; o > 0; o >>= 1) w = fminf(w, __shfl_xor_sync(0xffffffffu, w, o));
    __shared__ float sr[2];
    if ((f & 31) == 0) sr[f >> 5] = w;
    __syncthreads();
    if (f == 0) atomicMin(&g_min_key, fkey(fminf(sr[0], sr[1])));
}

// ---------------- K4: final pool finish + BatchNorm(momentum=1) ----------------
__global__ void __launch_bounds__(64) k_final(const float* opW, const float* opb, float* out) {
    pool_finish(LL - 1, opW, opb);
    __syncthreads();
    int t = threadIdx.x;
    if (t < 32) {
        float s0 = g_scores[t], s1 = g_scores[32 + t];
        float m = 0.5f*(s0 + s1);
        float v = 0.5f*((s0 - m)*(s0 - m) + (s1 - m)*(s1 - m));
        float r = rsqrtf(v + EPSL);
        out[t]      = (s0 - m)*r;
        out[32 + t] = (s1 - m)*r;
    }
}

// ---------------- launch ----------------
extern "C" void kernel_launch(void* const* d_in, const int* in_sizes, int n_in,
                              void* d_out, int out_size) {
    const int*   ei    = (const int*)  d_in[0];
    const float* W0    = (const float*)d_in[2];
    const float* b0    = (const float*)d_in[3];
    const float* Ws    = (const float*)d_in[4];
    const float* bs    = (const float*)d_in[5];
    const float* ln_g  = (const float*)d_in[6];
    const float* ln_b  = (const float*)d_in[7];
    const float* fW0   = (const float*)d_in[8];
    const float* fb0   = (const float*)d_in[9];
    const float* fWs   = (const float*)d_in[10];
    const float* fbs   = (const float*)d_in[11];
    const float* fln_g = (const float*)d_in[12];
    const float* fln_b = (const float*)d_in[13];
    const float* opW   = (const float*)d_in[14];
    const float* opb   = (const float*)d_in[15];
    int E = in_sizes[0] / 2;

    k_init<<<1, 256>>>(ei, E);
    for (int l = 0; l < LL; l++) {
        k_h<<<CELLS + 1, 64>>>(l, W0, b0, Ws, bs, opW, opb);
        k_attn<<<CELLS, 64>>>(l, ln_g, ln_b, fW0, fb0, fWs, fbs, fln_g, fln_b);
        k_pool_reduce<<<BB*NN, 64>>>();
    }
    k_final<<<1, 64>>>(opW, opb, (float*)d_out);
}

// round 3
// speedup vs baseline: 1.0862x; 1.0862x over previous
#include <cuda_runtime.h>
#include <cuda_bf16.h>

#define BB   2
#define NN   32
#define LL   4
#define ED   64
#define HD   16
#define EPSL 1e-5f
#define CELLS (BB*NN*NN)          // 2048
#define GRID 256
#define TPB  256
#define YT   8                     // y-tile per block (4 blocks per (b,x))
#define STR  68                    // padded slab row stride (floats)

// ---------------- device scratch ----------------
__device__ __align__(16) float g_adj[CELLS];
__device__ __align__(16) float g_x[CELLS*ED];
__device__ __align__(16) float g_h[CELLS*ED];
__device__ __align__(16) float g_q[CELLS*ED];
__device__ float    g_scores[BB*32];
__device__ unsigned g_diag_key[BB*ED];
__device__ unsigned g_off_key [BB*ED];
__device__ unsigned g_min_key;
__device__ int g_cnt;
__device__ int g_gen;

__device__ __forceinline__ unsigned fkey(float f) {
    unsigned u = __float_as_uint(f);
    return (u & 0x80000000u) ? ~u : (u | 0x80000000u);
}
__device__ __forceinline__ float funkey(unsigned k) {
    unsigned u = (k & 0x80000000u) ? (k & 0x7fffffffu) : ~k;
    return __uint_as_float(u);
}

// ---- software grid barrier (all GRID blocks co-resident via launch_bounds) ----
__device__ __forceinline__ void gsync() {
    __syncthreads();
    if (threadIdx.x == 0) {
        __threadfence();                       // publish writes + L1D invalidate
        int g = *(volatile int*)&g_gen;        // read gen BEFORE arrival
        if (atomicAdd(&g_cnt, 1) == GRID - 1) {
            g_cnt = 0;
            __threadfence();
            atomicExch(&g_gen, g + 1);
        } else {
            while (*(volatile int*)&g_gen == g) {}
        }
        __threadfence();                       // acquire + L1D invalidate
    }
    __syncthreads();
}

// ---- pool finish: consume keys -> scores, reset keys (one block, 256 thr) ----
__device__ void pool_finish_f(int layer, const float* opW, const float* opb,
                              float (*pooled)[128], float* sr2) {
    int t = threadIdx.x;
    float d0 = 0.f, d1 = 0.f, o0 = 0.f, o1 = 0.f, gmin = 0.f;
    if (t < 64) {
        d0 = funkey(g_diag_key[t]);   d1 = funkey(g_diag_key[64 + t]);
        o0 = funkey(g_off_key[t]);    o1 = funkey(g_off_key[64 + t]);
        gmin = funkey(g_min_key);
        float m = fmaxf(d0, d1);
        #pragma unroll
        for (int o = 16; o > 0; o >>= 1) m = fmaxf(m, __shfl_xor_sync(~0u, m, o));
        if ((t & 31) == 0) sr2[t >> 5] = m;
    }
    __syncthreads();
    if (t < 64) {
        float gdm = fmaxf(sr2[0], sr2[1]);
        float val = fabsf(gdm - gmin);
        pooled[0][t]      = d0;
        pooled[0][64 + t] = fmaxf(o0, d0 - val);
        pooled[1][t]      = d1;
        pooled[1][64 + t] = fmaxf(o1, d1 - val);
        g_diag_key[t] = 0u; g_diag_key[64 + t] = 0u;
        g_off_key [t] = 0u; g_off_key [64 + t] = 0u;
        if (t == 0) g_min_key = 0xFFFFFFFFu;
    }
    __syncthreads();
    if (t < 64) {
        int b = t >> 5, j = t & 31;
        const float* w = opW + (layer*32 + j) * 128;
        float acc = opb[layer*32 + j];
        #pragma unroll
        for (int k = 0; k < 128; k++) acc += pooled[b][k] * w[k];
        g_scores[b*32 + j] += acc;
    }
    __syncthreads();
}

// ---------------- THE megakernel ----------------
__global__ void __launch_bounds__(TPB, 2)
mega(const int* ei, int E,
     const float* W0, const float* b0, const float* Ws, const float* bs,
     const float* ln_g, const float* ln_b,
     const float* fW0, const float* fb0, const float* fWs, const float* fbs,
     const float* fln_g, const float* fln_b,
     const float* opW, const float* opb, float* out)
{
    __shared__ __align__(16) float shx[NN*STR];
    __shared__ __align__(16) float sqx[NN*STR];
    __shared__ __align__(16) float shy[NN*STR];
    __shared__ __align__(16) float sqy[NN*STR];
    __shared__ float ss[4][33], sm_[4][33], se_[4][33];
    __shared__ float watt[4][32], wc[4][32];
    __shared__ float pacc[4][64], pc[4][64];
    __shared__ float fred[4][64];
    __shared__ __align__(16) float sxu[64];
    __shared__ __align__(16) float sxold[64];
    __shared__ float slg[16], slb[16];
    __shared__ float sred[2], sred2[2];
    __shared__ float pooled[2][128];
    __shared__ int   sflag;

    int t = threadIdx.x;
    int blk = blockIdx.x;

    // ================= init (block 0) =================
    if (blk == 0) {
        float* sadj = shx;                     // 2048 <= 2176
        if (t == 0) sflag = 0;
        __syncthreads();
        for (int i = t; i < 512; i += TPB)
            if (ei[2*i + 1] != 0) sflag = 1;   // int32 vs int64 detection
        for (int i = t; i < CELLS; i += TPB) sadj[i] = 0.f;
        __syncthreads();
        int stride = sflag ? 1 : 2;
        for (int e = t; e < E; e += TPB) {
            int e0 = ei[stride*e];
            int e1 = ei[stride*E + stride*e];
            int g  = e0 >> 5;
            int ls = e0 - (g << 5);
            int ld = e1 - (g << 5);
            if (g >= 0 && g < BB && ld >= 0 && ld < NN)
                atomicAdd(&sadj[(g << 10) + (ls << 5) + ld], 1.f);
        }
        __syncthreads();
        if (t < BB*NN) { int b = t >> 5, n = t & 31; sadj[(b << 10) + n*33] = 2.f; }
        __syncthreads();
        for (int i = t; i < CELLS; i += TPB) g_adj[i] = sadj[i];
        if (t < 64)  g_scores[t] = 0.f;
        if (t < 128) { g_diag_key[t] = 0u; g_off_key[t] = 0u; }
        if (t == 0)  g_min_key = 0xFFFFFFFFu;
    }
    gsync();

    // ================= layers =================
    for (int l = 0; l < LL; l++) {
        // ---- pool finish of previous layer (overlapped; last block only) ----
        if (blk == GRID - 1 && l > 0)
            pool_finish_f(l - 1, opW, opb, pooled, sred);

        // ---- h + q phase: per 16-lane segment: h=x@W^T+b, q=LN(h) ----
        {
            int s = t >> 4, d = t & 15;
            int head = s & 3, cloc = s >> 2;   // 4 cells per iteration
            int f = head*16 + d;
            for (int it = 0; it < 2; it++) {
                int cell0 = (it*GRID + blk) * 4;
                int cell  = cell0 + cloc;
                float hf;
                if (l == 0) {
                    hf = g_adj[cell] * W0[f] + b0[f];
                } else {
                    __syncthreads();
                    shy[t] = g_x[cell0*64 + t];        // stage x for 4 cells
                    __syncthreads();
                    const float4* wr  = (const float4*)(Ws + (l-1)*4096 + f*64);
                    const float4* xv4 = (const float4*)shy + cloc*16;
                    float acc = bs[(l-1)*64 + f];
                    #pragma unroll
                    for (int j = 0; j < 16; j++) {
                        float4 w = wr[j], xv = xv4[j];
                        acc += w.x*xv.x + w.y*xv.y + w.z*xv.z + w.w*xv.w;
                    }
                    hf = acc;
                }
                // 16-lane LayerNorm
                float ssum = hf;
                #pragma unroll
                for (int o = 8; o > 0; o >>= 1) ssum += __shfl_xor_sync(~0u, ssum, o, 16);
                float mn = ssum * (1.f/16.f);
                float dd = hf - mn;
                float vv = dd*dd;
                #pragma unroll
                for (int o = 8; o > 0; o >>= 1) vv += __shfl_xor_sync(~0u, vv, o, 16);
                float rstd = rsqrtf(vv*(1.f/16.f) + EPSL);
                g_h[cell*64 + f] = hf;
                g_q[cell*64 + f] = dd*rstd*ln_g[l*16 + d] + ln_b[l*16 + d];
            }
        }
        gsync();

        // ---- attention + fused LN + FFN + LN + pooling accumulation ----
        {
            int pair = blk >> 2;
            int b = pair >> 5, x = pair & 31;
            int y0 = (blk & 3) * YT;
            int g = t >> 6, hh = (t >> 4) & 3, d = t & 15, f = t & 63;
            bool hasdiag = (x >= y0 && x < y0 + YT);

            const float4* hx = (const float4*)(g_h + ((b*32 + x)*32)*64);
            const float4* qx = (const float4*)(g_q + ((b*32 + x)*32)*64);
            for (int i = t; i < 512; i += TPB) {
                int a = i >> 4, j = i & 15;
                *(float4*)&shx[a*STR + j*4] = hx[i];
                *(float4*)&sqx[a*STR + j*4] = qx[i];
            }
            if (t < 16) { slg[t] = ln_g[l*16 + t]; slb[t] = ln_b[l*16 + t]; }

            float offm = -3.0e38f, minv = 3.0e38f, dval = 0.f;

            for (int yi = 0; yi < YT; yi++) {
                int y = y0 + yi;
                int cell = (b*32 + x)*32 + y;
                __syncthreads();
                for (int i = t; i < 512; i += TPB) {
                    int a = i >> 4, j = i & 15;
                    *(float4*)&shy[a*STR + j*4] =
                        *(const float4*)(g_h + ((b*32 + a)*32 + y)*64 + j*4);
                    *(float4*)&sqy[a*STR + j*4] =
                        *(const float4*)(g_q + ((b*32 + a)*32 + y)*64 + j*4);
                }
                if (l == 0) { if (t == 0) sxold[0] = g_adj[cell]; }
                else if (t < 64) sxold[t] = g_x[cell*64 + t];
                __syncthreads();

                // per-a stats (4-way parallel over a-chunks)
                #pragma unroll
                for (int ac = 0; ac < 8; ac++) {
                    int a = g*8 + ac;
                    float p  = shx[a*STR + f], r  = shy[a*STR + f];
                    float qp = sqx[a*STR + f], qr = sqy[a*STR + f];
                    float v1 = qp*qr, pr = p*r, v3 = pr*pr;
                    #pragma unroll
                    for (int o = 8; o > 0; o >>= 1) {
                        v1 += __shfl_xor_sync(~0u, v1, o, 16);
                        pr += __shfl_xor_sync(~0u, pr, o, 16);
                        v3 += __shfl_xor_sync(~0u, v3, o, 16);
                    }
                    if (d == 0) {
                        ss [hh][a] = v1 * 0.25f;
                        sm_[hh][a] = pr * (1.f/16.f);
                        se_[hh][a] = v3 * (1.f/16.f);
                    }
                }
                __syncthreads();

                // softmax weights, once per (h,a)
                if (t < 128) {
                    int h2 = t >> 5, a = t & 31;
                    float sv = ss[h2][a];
                    float mx = sv;
                    #pragma unroll
                    for (int o = 16; o > 0; o >>= 1) mx = fmaxf(mx, __shfl_xor_sync(~0u, mx, o));
                    float e = __expf(sv - mx);
                    float sume = e;
                    #pragma unroll
                    for (int o = 16; o > 0; o >>= 1) sume += __shfl_xor_sync(~0u, sume, o);
                    float att = e / sume;
                    float m = sm_[h2][a];
                    float rstd = rsqrtf(se_[h2][a] - m*m + EPSL);
                    watt[h2][a] = att * rstd;
                    wc  [h2][a] = att * m * rstd;
                }
                __syncthreads();

                // weighted contraction partials
                float acc = 0.f, cs = 0.f;
                #pragma unroll
                for (int ac = 0; ac < 8; ac++) {
                    int a = g*8 + ac;
                    acc += watt[hh][a] * shx[a*STR + f] * shy[a*STR + f];
                    cs  += wc[hh][a];
                }
                pacc[g][f] = acc; pc[g][f] = cs;
                __syncthreads();
                if (t < 64) {
                    float A = pacc[0][t] + pacc[1][t] + pacc[2][t] + pacc[3][t];
                    float C = pc[0][t] + pc[1][t] + pc[2][t] + pc[3][t];
                    sxu[t] = slg[t & 15] * (A - C) + slb[t & 15];
                }
                __syncthreads();

                // FFN on concat([x_old, xu])  (4-way split over k)
                float sp = 0.f;
                if (l == 0) {
                    const float* fw = fW0 + f*65;
                    if (g == 0) sp = fb0[f] + fw[0]*sxold[0];
                    #pragma unroll
                    for (int k = 0; k < 16; k++) sp += fw[1 + g*16 + k] * sxu[g*16 + k];
                } else {
                    const float4* fw4 = (const float4*)(fWs + (l-1)*8192 + f*128 + g*32);
                    const float4* v4  = (const float4*)((g < 2 ? sxold : sxu) + (g & 1)*32);
                    if (g == 0) sp = fbs[(l-1)*64 + f];
                    #pragma unroll
                    for (int k = 0; k < 8; k++) {
                        float4 w = fw4[k], xv = v4[k];
                        sp += w.x*xv.x + w.y*xv.y + w.z*xv.z + w.w*xv.w;
                    }
                }
                fred[g][f] = sp;
                __syncthreads();

                // LN over ED + pooling accumulation
                float yv = 0.f, dv = 0.f;
                if (t < 64) {
                    yv = fred[0][t] + fred[1][t] + fred[2][t] + fred[3][t];
                    float ws = yv;
                    #pragma unroll
                    for (int o = 16; o > 0; o >>= 1) ws += __shfl_xor_sync(~0u, ws, o);
                    if ((t & 31) == 0) sred[t >> 5] = ws;
                }
                __syncthreads();
                if (t < 64) {
                    float mean = (sred[0] + sred[1]) * (1.f/64.f);
                    dv = yv - mean;
                    float w2 = dv*dv;
                    #pragma unroll
                    for (int o = 16; o > 0; o >>= 1) w2 += __shfl_xor_sync(~0u, w2, o);
                    if ((t & 31) == 0) sred2[t >> 5] = w2;
                }
                __syncthreads();
                if (t < 64) {
                    float var = (sred2[0] + sred2[1]) * (1.f/64.f);
                    float xn = dv * rsqrtf(var + EPSL) * fln_g[l*64 + t] + fln_b[l*64 + t];
                    g_x[cell*64 + t] = xn;
                    minv = fminf(minv, xn);
                    if (y == x) dval = xn;
                    else        offm = fmaxf(offm, xn);
                }
            } // y loop

            __syncthreads();
            if (t < 64) {
                atomicMax(&g_off_key[b*64 + t], fkey(offm));
                if (hasdiag) atomicMax(&g_diag_key[b*64 + t], fkey(dval));
                float w = minv;
                #pragma unroll
                for (int o = 16; o > 0; o >>= 1) w = fminf(w, __shfl_xor_sync(~0u, w, o));
                if ((t & 31) == 0) sred[t >> 5] = w;
            }
            __syncthreads();
            if (t == 0) atomicMin(&g_min_key, fkey(fminf(sred[0], sred[1])));
        }
        gsync();
    } // layer loop

    // ================= final: pool finish L-1 + BatchNorm =================
    if (blk == 0) {
        pool_finish_f(LL - 1, opW, opb, pooled, sred);
        __syncthreads();
        if (t < 32) {
            float s0 = g_scores[t], s1 = g_scores[32 + t];
            float m = 0.5f*(s0 + s1);
            float v = 0.5f*((s0 - m)*(s0 - m) + (s1 - m)*(s1 - m));
            float r = rsqrtf(v + EPSL);
            out[t]      = (s0 - m)*r;
            out[32 + t] = (s1 - m)*r;
        }
    }
}

// ---------------- launch ----------------
extern "C" void kernel_launch(void* const* d_in, const int* in_sizes, int n_in,
                              void* d_out, int out_size) {
    const int*   ei    = (const int*)  d_in[0];
    const float* W0    = (const float*)d_in[2];
    const float* b0    = (const float*)d_in[3];
    const float* Ws    = (const float*)d_in[4];
    const float* bs    = (const float*)d_in[5];
    const float* ln_g  = (const float*)d_in[6];
    const float* ln_b  = (const float*)d_in[7];
    const float* fW0   = (const float*)d_in[8];
    const float* fb0   = (const float*)d_in[9];
    const float* fWs   = (const float*)d_in[10];
    const float* fbs   = (const float*)d_in[11];
    const float* fln_g = (const float*)d_in[12];
    const float* fln_b = (const float*)d_in[13];
    const float* opW   = (const float*)d_in[14];
    const float* opb   = (const float*)d_in[15];
    int E = in_sizes[0] / 2;

    mega<<<GRID, TPB>>>(ei, E, W0, b0, Ws, bs, ln_g, ln_b,
                        fW0, fb0, fWs, fbs, fln_g, fln_b,
                        opW, opb, (float*)d_out);
}

// round 4
// speedup vs baseline: 1.3974x; 1.2865x over previous
#include <cuda_runtime.h>
#include <cuda_bf16.h>

#define BB   2
#define NN   32
#define LL   4
#define EPSL 1e-5f
#define CELLS (BB*NN*NN)          // 2048
#define GRID 256
#define TPB  256

// ---------------- device scratch ----------------
__device__ __align__(16) float g_adj[CELLS];
__device__ __align__(16) float g_x[CELLS*64];
__device__ __align__(16) float g_h[CELLS*64];
__device__ __align__(16) float g_q[CELLS*64];
__device__ float    g_scores[64];
__device__ unsigned g_diag_key[128];
__device__ unsigned g_off_key [128];
__device__ unsigned g_min_key;
__device__ int g_cnt;
__device__ int g_gen;

__device__ __forceinline__ unsigned fkey(float f) {
    unsigned u = __float_as_uint(f);
    return (u & 0x80000000u) ? ~u : (u | 0x80000000u);
}
__device__ __forceinline__ float funkey(unsigned k) {
    unsigned u = (k & 0x80000000u) ? (k & 0x7fffffffu) : ~k;
    return __uint_as_float(u);
}

// ---- software grid barrier (all GRID blocks co-resident) ----
__device__ __forceinline__ void gsync() {
    __syncthreads();
    if (threadIdx.x == 0) {
        __threadfence();
        int g = *(volatile int*)&g_gen;
        if (atomicAdd(&g_cnt, 1) == GRID - 1) {
            g_cnt = 0;
            __threadfence();
            atomicExch(&g_gen, g + 1);
        } else {
            while (*(volatile int*)&g_gen == g) {}
        }
        __threadfence();
    }
    __syncthreads();
}

// ---- pool finish: keys -> scores, reset keys (whole block, 256 thr) ----
__device__ void pool_finish_f(int layer, const float* opW, const float* opb,
                              float (*pooled)[128], float* sr2) {
    int t = threadIdx.x;
    float d0 = 0.f, d1 = 0.f, o0 = 0.f, o1 = 0.f, gmin = 0.f;
    if (t < 64) {
        d0 = funkey(g_diag_key[t]);   d1 = funkey(g_diag_key[64 + t]);
        o0 = funkey(g_off_key[t]);    o1 = funkey(g_off_key[64 + t]);
        gmin = funkey(g_min_key);
        float m = fmaxf(d0, d1);
        #pragma unroll
        for (int o = 16; o > 0; o >>= 1) m = fmaxf(m, __shfl_xor_sync(~0u, m, o));
        if ((t & 31) == 0) sr2[t >> 5] = m;
    }
    __syncthreads();
    if (t < 64) {
        float gdm = fmaxf(sr2[0], sr2[1]);
        float val = fabsf(gdm - gmin);
        pooled[0][t]      = d0;
        pooled[0][64 + t] = fmaxf(o0, d0 - val);
        pooled[1][t]      = d1;
        pooled[1][64 + t] = fmaxf(o1, d1 - val);
        g_diag_key[t] = 0u; g_diag_key[64 + t] = 0u;
        g_off_key [t] = 0u; g_off_key [64 + t] = 0u;
        if (t == 0) g_min_key = 0xFFFFFFFFu;
    }
    __syncthreads();
    if (t < 64) {
        int b = t >> 5, j = t & 31;
        const float4* w4 = (const float4*)(opW + (layer*32 + j) * 128);
        const float4* p4 = (const float4*)pooled[b];
        float acc = opb[layer*32 + j];
        #pragma unroll
        for (int k = 0; k < 32; k++) {
            float4 w = w4[k], p = p4[k];
            acc += w.x*p.x + w.y*p.y + w.z*p.z + w.w*p.w;
        }
        g_scores[b*32 + j] += acc;
    }
    __syncthreads();
}

// ---------------- megakernel ----------------
__global__ void __launch_bounds__(TPB, 2)
mega(const int* ei, int E,
     const float* W0, const float* b0, const float* Ws, const float* bs,
     const float* ln_g, const float* ln_b,
     const float* fW0, const float* fb0, const float* fWs, const float* fbs,
     const float* fln_g, const float* fln_b,
     const float* opW, const float* opb, float* out)
{
    __shared__ __align__(16) float ct[8][32*20];   // contraction scratch, 20KB
    __shared__ __align__(16) float sxu[2][64];
    __shared__ __align__(16) float sxold[2][64];
    __shared__ float sfr[2][2][64];
    __shared__ float slg[16], slb[16];
    __shared__ float sred[2][2], sred2[2][2];
    __shared__ float pooled[2][128];
    __shared__ float sstage[256];
    __shared__ float psr[2];
    __shared__ int   sflag;

    int t = threadIdx.x;
    int blk = blockIdx.x;

    // ================= init (block 0) =================
    if (blk == 0) {
        float* sadj = &ct[0][0];               // 2048 <= 5120
        if (t == 0) sflag = 0;
        __syncthreads();
        for (int i = t; i < 512; i += TPB)
            if (ei[2*i + 1] != 0) sflag = 1;   // int32 vs int64 detect
        for (int i = t; i < CELLS; i += TPB) sadj[i] = 0.f;
        __syncthreads();
        int stride = sflag ? 1 : 2;
        for (int e = t; e < E; e += TPB) {
            int e0 = ei[stride*e];
            int e1 = ei[stride*E + stride*e];
            int g  = e0 >> 5;
            int ls = e0 - (g << 5);
            int ld = e1 - (g << 5);
            if (g >= 0 && g < BB && ld >= 0 && ld < NN)
                atomicAdd(&sadj[(g << 10) + (ls << 5) + ld], 1.f);
        }
        __syncthreads();
        if (t < BB*NN) { int b = t >> 5, n = t & 31; sadj[(b << 10) + n*33] = 2.f; }
        __syncthreads();
        for (int i = t; i < CELLS; i += TPB) g_adj[i] = sadj[i];
        if (t < 64)  g_scores[t] = 0.f;
        if (t < 128) { g_diag_key[t] = 0u; g_off_key[t] = 0u; }
        if (t == 0)  g_min_key = 0xFFFFFFFFu;
    }
    gsync();

    // ================= layers =================
    for (int l = 0; l < LL; l++) {
        // ---- pool finish of previous layer (block GRID-1 only) ----
        if (blk == GRID - 1 && l > 0)
            pool_finish_f(l - 1, opW, opb, pooled, psr);

        // ---- h + q phase ----
        {
            int s = t >> 4, d = t & 15;
            int head = s & 3, cloc = s >> 2;
            int f = head*16 + d;
            for (int it = 0; it < 2; it++) {
                int cell0 = (it*GRID + blk) * 4;
                int cell  = cell0 + cloc;
                float hf;
                if (l == 0) {
                    hf = g_adj[cell] * W0[f] + b0[f];
                } else {
                    __syncthreads();
                    sstage[t] = g_x[cell0*64 + t];
                    __syncthreads();
                    const float4* wr  = (const float4*)(Ws + (l-1)*4096 + f*64);
                    const float4* xv4 = (const float4*)sstage + cloc*16;
                    float acc = bs[(l-1)*64 + f];
                    #pragma unroll
                    for (int j = 0; j < 16; j++) {
                        float4 w = wr[j], xv = xv4[j];
                        acc += w.x*xv.x + w.y*xv.y + w.z*xv.z + w.w*xv.w;
                    }
                    hf = acc;
                }
                float ssum = hf;
                #pragma unroll
                for (int o = 8; o > 0; o >>= 1) ssum += __shfl_xor_sync(~0u, ssum, o, 16);
                float mn = ssum * (1.f/16.f);
                float dd = hf - mn;
                float vv = dd*dd;
                #pragma unroll
                for (int o = 8; o > 0; o >>= 1) vv += __shfl_xor_sync(~0u, vv, o, 16);
                float rstd = rsqrtf(vv*(1.f/16.f) + EPSL);
                g_h[cell*64 + f] = hf;
                g_q[cell*64 + f] = dd*rstd*ln_g[l*16 + d] + ln_b[l*16 + d];
            }
        }
        gsync();

        // ---- attention + fused LN(xu) + FFN + LN + pooling ----
        {
            int pair = blk >> 2;
            int b = pair >> 5, x = pair & 31;
            int y0 = (blk & 3) * 8;
            int ypar = t >> 7;                 // y-group 0/1
            int wg   = (t >> 5) & 3;           // head
            int a    = t & 31;                 // attention index
            int tf   = t & 127;                // id within group
            int barid = 1 + ypar;

            if (t < 16) { slg[t] = ln_g[l*16 + t]; slb[t] = ln_b[l*16 + t]; }

            // x-slab in registers (constant over y)
            float hxr[16], qxr[16];
            {
                const float4* hp = (const float4*)(g_h + (((b*32 + x)*32 + a)*64 + wg*16));
                const float4* qp = (const float4*)(g_q + (((b*32 + x)*32 + a)*64 + wg*16));
                #pragma unroll
                for (int j = 0; j < 4; j++) {
                    float4 v = hp[j];
                    hxr[4*j] = v.x; hxr[4*j+1] = v.y; hxr[4*j+2] = v.z; hxr[4*j+3] = v.w;
                    float4 q = qp[j];
                    qxr[4*j] = q.x; qxr[4*j+1] = q.y; qxr[4*j+2] = q.z; qxr[4*j+3] = q.w;
                }
            }
            __syncthreads();                   // slg/slb visible to all

            float offm = -3.0e38f, minv = 3.0e38f, dval = -3.0e38f;
            bool sawdiag = false;

            for (int yi = 0; yi < 4; yi++) {
                int y = y0 + 2*yi + ypar;
                int cell = (b*32 + x)*32 + y;

                // y-slab registers
                float hyr[16], qyr[16];
                {
                    const float4* hp = (const float4*)(g_h + (((b*32 + a)*32 + y)*64 + wg*16));
                    const float4* qp = (const float4*)(g_q + (((b*32 + a)*32 + y)*64 + wg*16));
                    #pragma unroll
                    for (int j = 0; j < 4; j++) {
                        float4 v = hp[j];
                        hyr[4*j] = v.x; hyr[4*j+1] = v.y; hyr[4*j+2] = v.z; hyr[4*j+3] = v.w;
                        float4 q = qp[j];
                        qyr[4*j] = q.x; qyr[4*j+1] = q.y; qyr[4*j+2] = q.z; qyr[4*j+3] = q.w;
                    }
                }
                // stage x_old for FFN (warp 0 of each group)
                if (wg == 0) {
                    if (l == 0) { if (a == 0) sxold[ypar][0] = g_adj[cell]; }
                    else {
                        sxold[ypar][a]      = g_x[cell*64 + a];
                        sxold[ypar][a + 32] = g_x[cell*64 + a + 32];
                    }
                }

                // stats: register dots, zero shuffles
                float s = 0.f, m = 0.f, e = 0.f;
                #pragma unroll
                for (int d = 0; d < 16; d++) {
                    s += qxr[d]*qyr[d];
                    float pr = hxr[d]*hyr[d];
                    m += pr;
                    e += pr*pr;
                }
                s *= 0.25f;
                // softmax over a (= warp lanes)
                float mx = s;
                #pragma unroll
                for (int o = 16; o > 0; o >>= 1) mx = fmaxf(mx, __shfl_xor_sync(~0u, mx, o));
                float ex = __expf(s - mx);
                float sume = ex;
                #pragma unroll
                for (int o = 16; o > 0; o >>= 1) sume += __shfl_xor_sync(~0u, sume, o);
                float att = ex / sume;
                float mm = m * (1.f/16.f);
                float rstd = rsqrtf(e*(1.f/16.f) - mm*mm + EPSL);
                float watt = att * rstd;
                float wcv  = att * mm * rstd;
                float wcs = wcv;
                #pragma unroll
                for (int o = 16; o > 0; o >>= 1) wcs += __shfl_xor_sync(~0u, wcs, o);

                // contraction: smem transpose + per-lane a-sum
                float* cp = &ct[ypar*4 + wg][a*20];
                #pragma unroll
                for (int j = 0; j < 4; j++) {
                    float4 v;
                    v.x = watt*hxr[4*j  ]*hyr[4*j  ];
                    v.y = watt*hxr[4*j+1]*hyr[4*j+1];
                    v.z = watt*hxr[4*j+2]*hyr[4*j+2];
                    v.w = watt*hxr[4*j+3]*hyr[4*j+3];
                    *(float4*)(cp + 4*j) = v;
                }
                __syncwarp();
                {
                    int dd = a & 15, half = a >> 4;
                    float acc = 0.f;
                    const float* cb = &ct[ypar*4 + wg][0];
                    #pragma unroll
                    for (int aa = 0; aa < 16; aa++)
                        acc += cb[(aa*2 + half)*20 + dd];
                    acc += __shfl_xor_sync(~0u, acc, 16);
                    if (a < 16)
                        sxu[ypar][wg*16 + a] = slg[a]*(acc - wcs) + slb[a];
                }
                asm volatile("bar.sync %0, %1;" :: "r"(barid), "r"(128) : "memory");

                // FFN: 2 threads per output f (halves of concat)
                {
                    int f = tf & 63, half = tf >> 6;
                    float sp;
                    if (l == 0) {
                        if (half == 0) sp = fb0[f] + fW0[f*65]*sxold[0 + ypar][0];
                        else {
                            sp = 0.f;
                            const float* fw = fW0 + f*65 + 1;
                            #pragma unroll
                            for (int k = 0; k < 64; k++) sp += fw[k]*sxu[ypar][k];
                        }
                    } else {
                        const float4* fw4 = (const float4*)(fWs + (l-1)*8192 + f*128 + half*64);
                        const float4* v4  = (const float4*)(half ? sxu[ypar] : sxold[ypar]);
                        sp = half ? 0.f : fbs[(l-1)*64 + f];
                        #pragma unroll
                        for (int j = 0; j < 16; j++) {
                            float4 w = fw4[j], xv = v4[j];
                            sp += w.x*xv.x + w.y*xv.y + w.z*xv.z + w.w*xv.w;
                        }
                    }
                    sfr[ypar][half][f] = sp;
                }
                asm volatile("bar.sync %0, %1;" :: "r"(barid), "r"(128) : "memory");

                // LN over 64 + write + pooling
                float yv = 0.f, dv = 0.f;
                if (tf < 64) {
                    yv = sfr[ypar][0][tf] + sfr[ypar][1][tf];
                    float ws = yv;
                    #pragma unroll
                    for (int o = 16; o > 0; o >>= 1) ws += __shfl_xor_sync(~0u, ws, o);
                    if ((tf & 31) == 0) sred[ypar][tf >> 5] = ws;
                }
                asm volatile("bar.sync %0, %1;" :: "r"(barid), "r"(128) : "memory");
                if (tf < 64) {
                    float mean = (sred[ypar][0] + sred[ypar][1]) * (1.f/64.f);
                    dv = yv - mean;
                    float w2 = dv*dv;
                    #pragma unroll
                    for (int o = 16; o > 0; o >>= 1) w2 += __shfl_xor_sync(~0u, w2, o);
                    if ((tf & 31) == 0) sred2[ypar][tf >> 5] = w2;
                }
                asm volatile("bar.sync %0, %1;" :: "r"(barid), "r"(128) : "memory");
                if (tf < 64) {
                    float var = (sred2[ypar][0] + sred2[ypar][1]) * (1.f/64.f);
                    float xn = dv * rsqrtf(var + EPSL) * fln_g[l*64 + tf] + fln_b[l*64 + tf];
                    g_x[cell*64 + tf] = xn;
                    minv = fminf(minv, xn);
                    if (y == x) { dval = xn; sawdiag = true; }
                    else offm = fmaxf(offm, xn);
                }
            } // y loop

            if (tf < 64) {
                atomicMax(&g_off_key[b*64 + tf], fkey(offm));
                if (sawdiag) atomicMax(&g_diag_key[b*64 + tf], fkey(dval));
                float w = minv;
                #pragma unroll
                for (int o = 16; o > 0; o >>= 1) w = fminf(w, __shfl_xor_sync(~0u, w, o));
                if ((tf & 31) == 0) atomicMin(&g_min_key, fkey(w));
            }
        }
        gsync();
    } // layers

    // ================= final =================
    if (blk == 0) {
        pool_finish_f(LL - 1, opW, opb, pooled, psr);
        __syncthreads();
        if (t < 32) {
            float s0 = g_scores[t], s1 = g_scores[32 + t];
            float m = 0.5f*(s0 + s1);
            float v = 0.5f*((s0 - m)*(s0 - m) + (s1 - m)*(s1 - m));
            float r = rsqrtf(v + EPSL);
            out[t]      = (s0 - m)*r;
            out[32 + t] = (s1 - m)*r;
        }
    }
}

// ---------------- launch ----------------
extern "C" void kernel_launch(void* const* d_in, const int* in_sizes, int n_in,
                              void* d_out, int out_size) {
    const int*   ei    = (const int*)  d_in[0];
    const float* W0    = (const float*)d_in[2];
    const float* b0    = (const float*)d_in[3];
    const float* Ws    = (const float*)d_in[4];
    const float* bs    = (const float*)d_in[5];
    const float* ln_g  = (const float*)d_in[6];
    const float* ln_b  = (const float*)d_in[7];
    const float* fW0   = (const float*)d_in[8];
    const float* fb0   = (const float*)d_in[9];
    const float* fWs   = (const float*)d_in[10];
    const float* fbs   = (const float*)d_in[11];
    const float* fln_g = (const float*)d_in[12];
    const float* fln_b = (const float*)d_in[13];
    const float* opW   = (const float*)d_in[14];
    const float* opb   = (const float*)d_in[15];
    int E = in_sizes[0] / 2;

    mega<<<GRID, TPB>>>(ei, E, W0, b0, Ws, bs, ln_g, ln_b,
                        fW0, fb0, fWs, fbs, fln_g, fln_b,
                        opW, opb, (float*)d_out);
}

// round 5
// speedup vs baseline: 2.2443x; 1.6060x over previous
#include <cuda_runtime.h>
#include <cuda_bf16.h>

#define BB   2
#define NN   32
#define LL   4
#define EPSL 1e-5f
#define CELLS (BB*NN*NN)          // 2048
#define GRID 256
#define TPB  256

// dynamic smem layout (floats)
#define OFF_CT  0                  // 8 warps x 640 (contraction) | sW 64x68 | sadj 2048
#define OFF_FW  5120               // FFN weights 64x132
#define OFF_HY  13568              // 2 groups x 32x68
#define DYNF    17920
#define DYNB    (DYNF*4)

// ---------------- device scratch ----------------
__device__ __align__(16) float g_adj[CELLS];
__device__ __align__(16) float g_x[CELLS*64];
__device__ __align__(16) float g_h[CELLS*64];
__device__ float    g_scores[64];
__device__ unsigned g_diag_key[128];
__device__ unsigned g_off_key [128];
__device__ unsigned g_min_key;
__device__ int g_cnt;
__device__ int g_gen;

__device__ __forceinline__ unsigned fkey(float f) {
    unsigned u = __float_as_uint(f);
    return (u & 0x80000000u) ? ~u : (u | 0x80000000u);
}
__device__ __forceinline__ float funkey(unsigned k) {
    unsigned u = (k & 0x80000000u) ? (k & 0x7fffffffu) : ~k;
    return __uint_as_float(u);
}

// ---- software grid barrier ----
__device__ __forceinline__ void gsync() {
    __syncthreads();
    if (threadIdx.x == 0) {
        __threadfence();
        int g = *(volatile int*)&g_gen;
        if (atomicAdd(&g_cnt, 1) == GRID - 1) {
            g_cnt = 0;
            __threadfence();
            atomicExch(&g_gen, g + 1);
        } else {
            while (*(volatile int*)&g_gen == g) __nanosleep(64);
        }
        __threadfence();
    }
    __syncthreads();
}

// ---- pool finish ----
__device__ void pool_finish_f(int layer, const float* opW, const float* opb,
                              float (*pooled)[128], float* sr2) {
    int t = threadIdx.x;
    float d0 = 0.f, d1 = 0.f, o0 = 0.f, o1 = 0.f, gmin = 0.f;
    if (t < 64) {
        d0 = funkey(g_diag_key[t]);   d1 = funkey(g_diag_key[64 + t]);
        o0 = funkey(g_off_key[t]);    o1 = funkey(g_off_key[64 + t]);
        gmin = funkey(g_min_key);
        float m = fmaxf(d0, d1);
        #pragma unroll
        for (int o = 16; o > 0; o >>= 1) m = fmaxf(m, __shfl_xor_sync(~0u, m, o));
        if ((t & 31) == 0) sr2[t >> 5] = m;
    }
    __syncthreads();
    if (t < 64) {
        float gdm = fmaxf(sr2[0], sr2[1]);
        float val = fabsf(gdm - gmin);
        pooled[0][t]      = d0;
        pooled[0][64 + t] = fmaxf(o0, d0 - val);
        pooled[1][t]      = d1;
        pooled[1][64 + t] = fmaxf(o1, d1 - val);
        g_diag_key[t] = 0u; g_diag_key[64 + t] = 0u;
        g_off_key [t] = 0u; g_off_key [64 + t] = 0u;
        if (t == 0) g_min_key = 0xFFFFFFFFu;
    }
    __syncthreads();
    if (t < 64) {
        int b = t >> 5, j = t & 31;
        const float* w = opW + (layer*32 + j) * 128;
        float acc = opb[layer*32 + j];
        #pragma unroll
        for (int k = 0; k < 128; k++) acc += pooled[b][k] * w[k];
        g_scores[b*32 + j] += acc;
    }
    __syncthreads();
}

#define GBAR() asm volatile("bar.sync %0, %1;" :: "r"(barid), "r"(128) : "memory")

// ---------------- megakernel ----------------
__global__ void __launch_bounds__(TPB, 2)
mega(const int* ei, int E,
     const float* W0, const float* b0, const float* Ws, const float* bs,
     const float* ln_g, const float* ln_b,
     const float* fW0, const float* fb0, const float* fWs, const float* fbs,
     const float* fln_g, const float* fln_b,
     const float* opW, const float* opb, float* out)
{
    extern __shared__ __align__(16) float dyn[];
    __shared__ __align__(16) float sxu[2][64];
    __shared__ __align__(16) float sxold[2][64];
    __shared__ float sfr[2][2][64];
    __shared__ float slg[16], slb[16];
    __shared__ float sred[2][2], sred2[2][2];
    __shared__ float pooled[2][128];
    __shared__ float sstage[256];
    __shared__ float sfw0[64];
    __shared__ float psr[2];
    __shared__ int   sflag;

    int t = threadIdx.x;
    int blk = blockIdx.x;

    // ================= init (block 0) =================
    if (blk == 0) {
        float* sadj = dyn;
        if (t == 0) sflag = 0;
        __syncthreads();
        for (int i = t; i < 512; i += TPB)
            if (ei[2*i + 1] != 0) sflag = 1;   // int32 vs int64 detect
        for (int i = t; i < CELLS; i += TPB) sadj[i] = 0.f;
        __syncthreads();
        int stride = sflag ? 1 : 2;
        for (int e = t; e < E; e += TPB) {
            int e0 = ei[stride*e];
            int e1 = ei[stride*E + stride*e];
            int g  = e0 >> 5;
            int ls = e0 - (g << 5);
            int ld = e1 - (g << 5);
            if (g >= 0 && g < BB && ld >= 0 && ld < NN)
                atomicAdd(&sadj[(g << 10) + (ls << 5) + ld], 1.f);
        }
        __syncthreads();
        if (t < BB*NN) { int b = t >> 5, n = t & 31; sadj[(b << 10) + n*33] = 2.f; }
        __syncthreads();
        for (int i = t; i < CELLS; i += TPB) g_adj[i] = sadj[i];
        if (t < 64)  g_scores[t] = 0.f;
        if (t < 128) { g_diag_key[t] = 0u; g_off_key[t] = 0u; }
        if (t == 0)  g_min_key = 0xFFFFFFFFu;
    }
    gsync();

    // ================= layers =================
    for (int l = 0; l < LL; l++) {
        if (blk == GRID - 1 && l > 0)
            pool_finish_f(l - 1, opW, opb, pooled, psr);

        // ---- h phase: h = x @ W^T + b ----
        {
            int cloc = t >> 6, f = t & 63;
            if (l > 0) {
                // stage W (64x64) into dyn[OFF_CT] at stride 68 (coalesced)
                for (int i = t; i < 4096; i += TPB)
                    dyn[(i >> 6)*68 + (i & 63)] = Ws[(l-1)*4096 + i];
                __syncthreads();
            }
            for (int it = 0; it < 2; it++) {
                int cell0 = (it*GRID + blk) * 4;
                int cell  = cell0 + cloc;
                float hf;
                if (l == 0) {
                    hf = g_adj[cell] * W0[f] + b0[f];
                } else {
                    __syncthreads();
                    sstage[t] = g_x[cell0*64 + t];
                    __syncthreads();
                    const float4* xv4 = (const float4*)sstage + cloc*16;
                    float acc = bs[(l-1)*64 + f];
                    #pragma unroll
                    for (int j = 0; j < 16; j++) {
                        float4 w = *(const float4*)&dyn[f*68 + 4*j];
                        float4 xv = xv4[j];
                        acc += w.x*xv.x + w.y*xv.y + w.z*xv.z + w.w*xv.w;
                    }
                    hf = acc;
                }
                g_h[cell*64 + f] = hf;
            }
        }
        gsync();

        // ---- attention + fused LN(xu) + FFN + LN + pooling ----
        {
            int pair = blk >> 2;
            int b = pair >> 5, x = pair & 31;
            int y0 = (blk & 3) * 8;
            int ypar = t >> 7;                 // y-group 0/1
            int wg   = (t >> 5) & 3;           // head
            int a    = t & 31;                 // attention index
            int tf   = t & 127;
            int barid = 1 + ypar;
            float* shy = dyn + OFF_HY + ypar*2176;
            float* ctw = dyn + OFF_CT + (ypar*4 + wg)*640;

            // stage FFN weights coalesced at stride 132
            if (l == 0) {
                for (int i = t; i < 4096; i += TPB)
                    dyn[OFF_FW + (i >> 6)*132 + (i & 63)] = fW0[(i >> 6)*65 + 1 + (i & 63)];
                if (t < 64) sfw0[t] = fW0[t*65];
            } else {
                for (int i = t; i < 8192; i += TPB)
                    dyn[OFF_FW + (i >> 7)*132 + (i & 127)] = fWs[(l-1)*8192 + i];
            }
            if (t < 16) { slg[t] = ln_g[l*16 + t]; slb[t] = ln_b[l*16 + t]; }

            // stage x-slab (contiguous) into shy, coalesced
            {
                const float4* xb = (const float4*)(g_h + ((b*32 + x)*32)*64);
                for (int v = tf; v < 512; v += 128) {
                    int row = v >> 4, c4 = (v & 15)*4;
                    *(float4*)&shy[row*68 + c4] = xb[v];
                }
            }
            __syncthreads();

            // x-side registers: hxr + folded q constants
            float hxr[16], gq[16];
            float A = 0.f, Bc = 0.f;
            {
                #pragma unroll
                for (int j = 0; j < 4; j++) {
                    float4 v = *(const float4*)&shy[a*68 + wg*16 + 4*j];
                    hxr[4*j] = v.x; hxr[4*j+1] = v.y; hxr[4*j+2] = v.z; hxr[4*j+3] = v.w;
                }
                float s0 = 0.f, s1 = 0.f;
                #pragma unroll
                for (int d = 0; d < 16; d++) { s0 += hxr[d]; s1 += hxr[d]*hxr[d]; }
                float mn = s0 * (1.f/16.f);
                float rstd = rsqrtf(s1*(1.f/16.f) - mn*mn + EPSL);
                #pragma unroll
                for (int d = 0; d < 16; d++) {
                    float qx = (hxr[d] - mn)*rstd*slg[d] + slb[d];
                    gq[d] = qx * slg[d];
                    A  += gq[d];
                    Bc += qx * slb[d];
                }
            }

            float offm = -3.0e38f, minv = 3.0e38f, dval = -3.0e38f;
            bool sawdiag = false;

            const float* hyb = g_h + (b*32)*32*64;   // + a*2048 + y*64

            for (int yi = 0; yi < 4; yi++) {
                int y = y0 + 2*yi + ypar;
                int cell = (b*32 + x)*32 + y;

                GBAR();                          // shy / sxu / sfr reuse safe
                // stage y-slab coalesced
                for (int v = tf; v < 512; v += 128) {
                    int row = v >> 4, c4 = (v & 15)*4;
                    *(float4*)&shy[row*68 + c4] = *(const float4*)(hyb + row*2048 + y*64 + c4);
                }
                if (wg == 0) {                   // stage x_old
                    if (l == 0) { if (a == 0) sxold[ypar][0] = g_adj[cell]; }
                    else {
                        sxold[ypar][a]      = g_x[cell*64 + a];
                        sxold[ypar][a + 32] = g_x[cell*64 + a + 32];
                    }
                }
                GBAR();

                // y-side registers + stats
                float hyr[16];
                #pragma unroll
                for (int j = 0; j < 4; j++) {
                    float4 v = *(const float4*)&shy[a*68 + wg*16 + 4*j];
                    hyr[4*j] = v.x; hyr[4*j+1] = v.y; hyr[4*j+2] = v.z; hyr[4*j+3] = v.w;
                }
                float s0 = 0.f, s1 = 0.f, dg = 0.f, mprod = 0.f, eprod = 0.f;
                #pragma unroll
                for (int d = 0; d < 16; d++) {
                    s0 += hyr[d];
                    s1 += hyr[d]*hyr[d];
                    dg += gq[d]*hyr[d];
                    float pr = hxr[d]*hyr[d];
                    mprod += pr;
                    eprod += pr*pr;
                }
                float mny = s0 * (1.f/16.f);
                float rsy = rsqrtf(s1*(1.f/16.f) - mny*mny + EPSL);
                float s = (rsy*(dg - mny*A) + Bc) * 0.25f;
                float mm = mprod * (1.f/16.f);
                float rstd = rsqrtf(eprod*(1.f/16.f) - mm*mm + EPSL);

                // softmax over a (warp lanes)
                float mx = s;
                #pragma unroll
                for (int o = 16; o > 0; o >>= 1) mx = fmaxf(mx, __shfl_xor_sync(~0u, mx, o));
                float ex = __expf(s - mx);
                float t2 = ex, t3 = ex * mm * rstd;
                #pragma unroll
                for (int o = 16; o > 0; o >>= 1) {
                    t2 += __shfl_xor_sync(~0u, t2, o);
                    t3 += __shfl_xor_sync(~0u, t3, o);
                }
                float inv = 1.f / t2;
                float watt = ex * rstd * inv;
                float wcs  = t3 * inv;           // sum over a of att*mm*rstd

                // contraction: warp-private smem transpose
                #pragma unroll
                for (int j = 0; j < 4; j++) {
                    float4 v;
                    v.x = watt*hxr[4*j  ]*hyr[4*j  ];
                    v.y = watt*hxr[4*j+1]*hyr[4*j+1];
                    v.z = watt*hxr[4*j+2]*hyr[4*j+2];
                    v.w = watt*hxr[4*j+3]*hyr[4*j+3];
                    *(float4*)&ctw[a*20 + 4*j] = v;
                }
                __syncwarp();
                {
                    int dd = a & 15, half = a >> 4;
                    float a0 = 0.f, a1 = 0.f, a2 = 0.f, a3 = 0.f;
                    #pragma unroll
                    for (int aa = 0; aa < 4; aa++) {
                        a0 += ctw[((aa     )*2 + half)*20 + dd];
                        a1 += ctw[((aa +  4)*2 + half)*20 + dd];
                        a2 += ctw[((aa +  8)*2 + half)*20 + dd];
                        a3 += ctw[((aa + 12)*2 + half)*20 + dd];
                    }
                    float acc = (a0 + a1) + (a2 + a3);
                    acc += __shfl_xor_sync(~0u, acc, 16);
                    if (a < 16)
                        sxu[ypar][wg*16 + a] = slg[a]*(acc - wcs) + slb[a];
                }
                GBAR();

                // FFN: 2 threads per output f
                {
                    int f = tf & 63, half = tf >> 6;
                    float sp;
                    if (l == 0 && half == 0) {
                        sp = fb0[f] + sfw0[f]*sxold[ypar][0];
                    } else {
                        const float* fw = &dyn[OFF_FW + f*132 + (l ? half*64 : 0)];
                        const float4* v4 = (const float4*)((l == 0 || half) ? sxu[ypar] : sxold[ypar]);
                        sp = (l && half == 0) ? fbs[(l-1)*64 + f] : 0.f;
                        #pragma unroll
                        for (int j = 0; j < 16; j++) {
                            float4 w = *(const float4*)&fw[4*j];
                            float4 xv = v4[j];
                            sp += w.x*xv.x + w.y*xv.y + w.z*xv.z + w.w*xv.w;
                        }
                    }
                    sfr[ypar][half][f] = sp;
                }
                GBAR();

                // LN over 64: fused (sum, sumsq) tree
                float yv = 0.f;
                if (tf < 64) {
                    yv = sfr[ypar][0][tf] + sfr[ypar][1][tf];
                    float w1 = yv, w2 = yv*yv;
                    #pragma unroll
                    for (int o = 16; o > 0; o >>= 1) {
                        w1 += __shfl_xor_sync(~0u, w1, o);
                        w2 += __shfl_xor_sync(~0u, w2, o);
                    }
                    if ((tf & 31) == 0) { sred[ypar][tf >> 5] = w1; sred2[ypar][tf >> 5] = w2; }
                }
                GBAR();
                if (tf < 64) {
                    float mean = (sred[ypar][0] + sred[ypar][1]) * (1.f/64.f);
                    float ms   = (sred2[ypar][0] + sred2[ypar][1]) * (1.f/64.f);
                    float var  = ms - mean*mean;
                    float dv = yv - mean;
                    float xn = dv * rsqrtf(var + EPSL) * fln_g[l*64 + tf] + fln_b[l*64 + tf];
                    g_x[cell*64 + tf] = xn;
                    minv = fminf(minv, xn);
                    if (y == x) { dval = xn; sawdiag = true; }
                    else offm = fmaxf(offm, xn);
                }
            } // y loop

            if (tf < 64) {
                atomicMax(&g_off_key[b*64 + tf], fkey(offm));
                if (sawdiag) atomicMax(&g_diag_key[b*64 + tf], fkey(dval));
                float w = minv;
                #pragma unroll
                for (int o = 16; o > 0; o >>= 1) w = fminf(w, __shfl_xor_sync(~0u, w, o));
                if ((tf & 31) == 0) atomicMin(&g_min_key, fkey(w));
            }
        }
        gsync();
    } // layers

    // ================= final =================
    if (blk == 0) {
        pool_finish_f(LL - 1, opW, opb, pooled, psr);
        __syncthreads();
        if (t < 32) {
            float s0 = g_scores[t], s1 = g_scores[32 + t];
            float m = 0.5f*(s0 + s1);
            float v = 0.5f*((s0 - m)*(s0 - m) + (s1 - m)*(s1 - m));
            float r = rsqrtf(v + EPSL);
            out[t]      = (s0 - m)*r;
            out[32 + t] = (s1 - m)*r;
        }
    }
}

// ---------------- launch ----------------
extern "C" void kernel_launch(void* const* d_in, const int* in_sizes, int n_in,
                              void* d_out, int out_size) {
    const int*   ei    = (const int*)  d_in[0];
    const float* W0    = (const float*)d_in[2];
    const float* b0    = (const float*)d_in[3];
    const float* Ws    = (const float*)d_in[4];
    const float* bs    = (const float*)d_in[5];
    const float* ln_g  = (const float*)d_in[6];
    const float* ln_b  = (const float*)d_in[7];
    const float* fW0   = (const float*)d_in[8];
    const float* fb0   = (const float*)d_in[9];
    const float* fWs   = (const float*)d_in[10];
    const float* fbs   = (const float*)d_in[11];
    const float* fln_g = (const float*)d_in[12];
    const float* fln_b = (const float*)d_in[13];
    const float* opW   = (const float*)d_in[14];
    const float* opb   = (const float*)d_in[15];
    int E = in_sizes[0] / 2;

    cudaFuncSetAttribute(mega, cudaFuncAttributeMaxDynamicSharedMemorySize, DYNB);
    mega<<<GRID, TPB, DYNB>>>(ei, E, W0, b0, Ws, bs, ln_g, ln_b,
                              fW0, fb0, fWs, fbs, fln_g, fln_b,
                              opW, opb, (float*)d_out);
}

// round 7
// speedup vs baseline: 3.0318x; 1.3509x over previous
#include <cuda_runtime.h>
#include <cuda_bf16.h>
#include <cuda_pipeline.h>

#define BB   2
#define NN   32
#define LL   4
#define EPSL 1e-5f
#define CELLS (BB*NN*NN)          // 2048
#define GRID 256
#define TPB  256

// dynamic smem layout (floats)
#define OFF_CT  0                  // 8x640 contraction | W 64x68 | opW 32x132 | sadj
#define OFF_FW  5120               // FFN weights 64x132
#define OFF_SY  13568              // 2 groups x 2 bufs x (32x68)
#define OFF_XO  22272              // 2 groups x 4 x 64 (x_old)
#define DYNF    22784
#define DYNB    (DYNF*4)

// ---------------- device scratch ----------------
__device__ __align__(16) float g_adj[CELLS];
__device__ __align__(16) float g_x[CELLS*64];
__device__ __align__(16) float g_h[CELLS*64];
__device__ float    g_scores[64];
__device__ unsigned g_diag_key[128];
__device__ unsigned g_off_key [128];
__device__ unsigned g_min_key;
__device__ int g_cnt;
__device__ int g_gen;

__device__ __forceinline__ unsigned fkey(float f) {
    unsigned u = __float_as_uint(f);
    return (u & 0x80000000u) ? ~u : (u | 0x80000000u);
}
__device__ __forceinline__ float funkey(unsigned k) {
    unsigned u = (k & 0x80000000u) ? (k & 0x7fffffffu) : ~k;
    return __uint_as_float(u);
}

// ---- software grid barrier ----
__device__ __forceinline__ void gsync() {
    __syncthreads();
    if (threadIdx.x == 0) {
        __threadfence();
        int g = *(volatile int*)&g_gen;
        if (atomicAdd(&g_cnt, 1) == GRID - 1) {
            g_cnt = 0;
            __threadfence();
            atomicExch(&g_gen, g + 1);
        } else {
            while (*(volatile int*)&g_gen == g) {}
        }
        __threadfence();
    }
    __syncthreads();
}

#define GBAR() asm volatile("bar.sync %0, %1;" :: "r"(barid), "r"(128) : "memory")

// ---- pool finish: keys -> scores (+reset), parallel dot, coalesced opW ----
__device__ void pool_finish2(int layer, const float* opW, const float* opb,
                             float* ct, float (*pooled)[128], float* psr,
                             float* psum) {
    int t = threadIdx.x;
    // stage opW layer slice 32x128 coalesced at stride 132
    for (int i = t; i < 1024; i += TPB)
        __pipeline_memcpy_async(&ct[(i >> 5)*132 + (i & 31)*4],
                                opW + layer*4096 + i*4, 16);
    __pipeline_commit();
    float d0 = 0.f, d1 = 0.f, o0 = 0.f, o1 = 0.f, gmin = 0.f;
    if (t < 64) {
        d0 = funkey(g_diag_key[t]);   d1 = funkey(g_diag_key[64 + t]);
        o0 = funkey(g_off_key[t]);    o1 = funkey(g_off_key[64 + t]);
        gmin = funkey(g_min_key);
        float m = fmaxf(d0, d1);
        #pragma unroll
        for (int o = 16; o > 0; o >>= 1) m = fmaxf(m, __shfl_xor_sync(~0u, m, o));
        if ((t & 31) == 0) psr[t >> 5] = m;
    }
    __syncthreads();
    if (t < 64) {
        float gdm = fmaxf(psr[0], psr[1]);
        float val = fabsf(gdm - gmin);
        pooled[0][t]      = d0;
        pooled[0][64 + t] = fmaxf(o0, d0 - val);
        pooled[1][t]      = d1;
        pooled[1][64 + t] = fmaxf(o1, d1 - val);
        g_diag_key[t] = 0u; g_diag_key[64 + t] = 0u;
        g_off_key [t] = 0u; g_off_key [64 + t] = 0u;
        if (t == 0) g_min_key = 0xFFFFFFFFu;
    }
    __pipeline_wait_prior(0);
    __syncthreads();
    // 4-way parallel dot: t = q*64 + bq*32 + j
    {
        int q = t >> 6, bj = t & 63, bq = bj >> 5, j = bj & 31;
        const float4* w4 = (const float4*)&ct[j*132 + q*32];
        const float4* p4 = (const float4*)&pooled[bq][q*32];
        float acc = 0.f;
        #pragma unroll
        for (int k = 0; k < 8; k++) {
            float4 w = w4[k], p = p4[k];
            acc += w.x*p.x + w.y*p.y + w.z*p.z + w.w*p.w;
        }
        psum[t] = acc;
    }
    __syncthreads();
    if (t < 64) {
        float s = psum[t] + psum[t + 64] + psum[t + 128] + psum[t + 192];
        g_scores[t] += s + opb[layer*32 + (t & 31)];
    }
    __syncthreads();
}

// ---------------- megakernel ----------------
__global__ void __launch_bounds__(TPB, 2)
mega(const int* ei, int E,
     const float* W0, const float* b0, const float* Ws, const float* bs,
     const float* ln_g, const float* ln_b,
     const float* fW0, const float* fb0, const float* fWs, const float* fbs,
     const float* fln_g, const float* fln_b,
     const float* opW, const float* opb, float* out)
{
    extern __shared__ __align__(16) float dyn[];
    __shared__ __align__(16) float sxu[2][64];
    __shared__ float sfr[2][2][64];
    __shared__ float slg[16], slb[16];
    __shared__ float sred[2][2], sred2[2][2];
    __shared__ float pooled[2][128];
    __shared__ __align__(16) float sstage[512];
    __shared__ float sfw0[64];
    __shared__ float psr[2];
    __shared__ int   sflag;

    int t = threadIdx.x;
    int blk = blockIdx.x;

    // ================= init (block 0) =================
    if (blk == 0) {
        float* sadj = dyn;
        if (t == 0) sflag = 0;
        __syncthreads();
        for (int i = t; i < 512; i += TPB)
            if (ei[2*i + 1] != 0) sflag = 1;   // int32 vs int64 detect
        for (int i = t; i < CELLS; i += TPB) sadj[i] = 0.f;
        __syncthreads();
        int stride = sflag ? 1 : 2;
        for (int e = t; e < E; e += TPB) {
            int e0 = ei[stride*e];
            int e1 = ei[stride*E + stride*e];
            int g  = e0 >> 5;
            int ls = e0 - (g << 5);
            int ld = e1 - (g << 5);
            if (g >= 0 && g < BB && ld >= 0 && ld < NN)
                atomicAdd(&sadj[(g << 10) + (ls << 5) + ld], 1.f);
        }
        __syncthreads();
        if (t < BB*NN) { int b = t >> 5, n = t & 31; sadj[(b << 10) + n*33] = 2.f; }
        __syncthreads();
        for (int i = t; i < CELLS; i += TPB) g_adj[i] = sadj[i];
        if (t < 64)  g_scores[t] = 0.f;
        if (t < 128) { g_diag_key[t] = 0u; g_off_key[t] = 0u; }
        if (t == 0)  g_min_key = 0xFFFFFFFFu;
    }
    gsync();

    // ================= layers =================
    for (int l = 0; l < LL; l++) {
        // ---- h phase (blocks 0..254) | pool finish (block 255) ----
        if (blk == GRID - 1) {
            if (l > 0) pool_finish2(l - 1, opW, opb, dyn, pooled, psr, sstage);
        } else {
            if (l > 0) {
                for (int i = t; i < 1024; i += TPB)
                    __pipeline_memcpy_async(&dyn[(i >> 4)*68 + (i & 15)*4],
                                            Ws + (l-1)*4096 + i*4, 16);
                __pipeline_commit();
            }
            for (int grp = blk; grp < 256; grp += GRID - 1) {
                int cell0 = grp * 8;
                if (l == 0) {
                    for (int o = t; o < 512; o += TPB) {
                        int cell = cell0 + (o >> 6), f = o & 63;
                        g_h[cell*64 + f] = g_adj[cell]*W0[f] + b0[f];
                    }
                } else {
                    if (t < 128)
                        __pipeline_memcpy_async(&sstage[t*4], g_x + cell0*64 + t*4, 16);
                    __pipeline_commit();
                    __pipeline_wait_prior(0);
                    __syncthreads();
                    int f = t & 63;
                    const float4* xr0 = (const float4*)(sstage + (t >> 6)*64);
                    const float4* xr1 = xr0 + 64;
                    float acc0 = bs[(l-1)*64 + f], acc1 = acc0;
                    #pragma unroll
                    for (int j = 0; j < 16; j++) {
                        float4 w = *(const float4*)&dyn[f*68 + 4*j];
                        float4 v0 = xr0[j], v1 = xr1[j];
                        acc0 += w.x*v0.x + w.y*v0.y + w.z*v0.z + w.w*v0.w;
                        acc1 += w.x*v1.x + w.y*v1.y + w.z*v1.z + w.w*v1.w;
                    }
                    int cell = cell0 + (t >> 6);
                    g_h[cell*64 + f]       = acc0;
                    g_h[(cell + 4)*64 + f] = acc1;
                    __syncthreads();
                }
            }
        }
        gsync();

        // ---- attention + fused LN(xu) + FFN + LN + pooling ----
        {
            int pair = blk >> 2;
            int b = pair >> 5, x = pair & 31;
            int y0 = (blk & 3) * 8;
            int ypar = t >> 7, wg = (t >> 5) & 3, a = t & 31, tf = t & 127;
            int barid = 1 + ypar;
            float* buf0 = dyn + OFF_SY + ypar*4352;
            float* buf1 = buf0 + 2176;
            float* ctw  = dyn + OFF_CT + (ypar*4 + wg)*640;
            float* sxo  = dyn + OFF_XO + ypar*256;

            // --- staging ---
            if (l == 0) {
                for (int i = t; i < 4096; i += TPB)
                    dyn[OFF_FW + (i >> 6)*132 + (i & 63)] = fW0[(i >> 6)*65 + 1 + (i & 63)];
                if (t < 64) sfw0[t] = fW0[t*65];
            } else {
                for (int i = t; i < 2048; i += TPB)
                    __pipeline_memcpy_async(&dyn[OFF_FW + (i >> 5)*132 + (i & 31)*4],
                                            fWs + (l-1)*8192 + i*4, 16);
            }
            {   // x-slab per group
                const float* xb = g_h + ((b*32 + x)*32)*64;
                for (int v = tf; v < 512; v += 128)
                    __pipeline_memcpy_async(&buf0[(v >> 4)*68 + (v & 15)*4], xb + v*4, 16);
            }
            if (l == 0) {
                if (tf < 4) sxo[tf*64] = g_adj[(b*32 + x)*32 + y0 + 2*tf + ypar];
            } else {
                if (tf < 64) {
                    int yi = tf >> 4, c4 = (tf & 15)*4;
                    __pipeline_memcpy_async(&sxo[yi*64 + c4],
                        g_x + (((b*32 + x)*32 + y0 + 2*yi + ypar))*64 + c4, 16);
                }
            }
            if (t < 16) { slg[t] = ln_g[l*16 + t]; slb[t] = ln_b[l*16 + t]; }
            __pipeline_commit();
            __pipeline_wait_prior(0);
            __syncthreads();

            // x-side registers: hxr + folded q constants
            float hxr[16], gq[16];
            float A = 0.f, Bc = 0.f;
            {
                #pragma unroll
                for (int j = 0; j < 4; j++) {
                    float4 v = *(const float4*)&buf0[a*68 + wg*16 + 4*j];
                    hxr[4*j] = v.x; hxr[4*j+1] = v.y; hxr[4*j+2] = v.z; hxr[4*j+3] = v.w;
                }
                float s0 = 0.f, s1 = 0.f;
                #pragma unroll
                for (int d = 0; d < 16; d++) { s0 += hxr[d]; s1 += hxr[d]*hxr[d]; }
                float mn = s0 * (1.f/16.f);
                float rstd = rsqrtf(s1*(1.f/16.f) - mn*mn + EPSL);
                #pragma unroll
                for (int d = 0; d < 16; d++) {
                    float qx = (hxr[d] - mn)*rstd*slg[d] + slb[d];
                    gq[d] = qx * slg[d];
                    A  += gq[d];
                    Bc += qx * slb[d];
                }
            }

            const float* hyb = g_h + (b*32)*32*64;
            {   // prefetch iter-0 y-slab into buf1
                int y = y0 + ypar;
                for (int v = tf; v < 512; v += 128)
                    __pipeline_memcpy_async(&buf1[(v >> 4)*68 + (v & 15)*4],
                                            hyb + (v >> 4)*2048 + y*64 + (v & 15)*4, 16);
                __pipeline_commit();
            }

            float offm = -3.0e38f, minv = 3.0e38f, dval = -3.0e38f;
            bool sawdiag = false;

            for (int i = 0; i < 4; i++) {
                int y = y0 + 2*i + ypar;
                int cell = (b*32 + x)*32 + y;
                float* cur = (i & 1) ? buf0 : buf1;
                float* nxt = (i & 1) ? buf1 : buf0;

                __pipeline_wait_prior(0);
                GBAR();                        // slab visible; prior buffers free

                float hyr[16];
                #pragma unroll
                for (int j = 0; j < 4; j++) {
                    float4 v = *(const float4*)&cur[a*68 + wg*16 + 4*j];
                    hyr[4*j] = v.x; hyr[4*j+1] = v.y; hyr[4*j+2] = v.z; hyr[4*j+3] = v.w;
                }
                if (i < 3) {                   // prefetch next y
                    int yn = y + 2;
                    for (int v = tf; v < 512; v += 128)
                        __pipeline_memcpy_async(&nxt[(v >> 4)*68 + (v & 15)*4],
                                                hyb + (v >> 4)*2048 + yn*64 + (v & 15)*4, 16);
                    __pipeline_commit();
                }

                // stats
                float s0 = 0.f, s1 = 0.f, dg = 0.f, mprod = 0.f, eprod = 0.f;
                #pragma unroll
                for (int d = 0; d < 16; d++) {
                    s0 += hyr[d];
                    s1 += hyr[d]*hyr[d];
                    dg += gq[d]*hyr[d];
                    float pr = hxr[d]*hyr[d];
                    mprod += pr;
                    eprod += pr*pr;
                }
                float mny = s0 * (1.f/16.f);
                float rsy = rsqrtf(s1*(1.f/16.f) - mny*mny + EPSL);
                float s = (rsy*(dg - mny*A) + Bc) * 0.25f;
                float mm = mprod * (1.f/16.f);
                float rstd = rsqrtf(eprod*(1.f/16.f) - mm*mm + EPSL);

                // softmax over a (no max-subtraction; LN-bounded scores)
                float ex = __expf(s);
                float t2 = ex, t3 = ex * mm * rstd;
                #pragma unroll
                for (int o = 16; o > 0; o >>= 1) {
                    t2 += __shfl_xor_sync(~0u, t2, o);
                    t3 += __shfl_xor_sync(~0u, t3, o);
                }
                float inv = 1.f / t2;
                float watt = ex * rstd * inv;
                float wcs  = t3 * inv;

                // contraction: warp-private smem transpose
                #pragma unroll
                for (int j = 0; j < 4; j++) {
                    float4 v;
                    v.x = watt*hxr[4*j  ]*hyr[4*j  ];
                    v.y = watt*hxr[4*j+1]*hyr[4*j+1];
                    v.z = watt*hxr[4*j+2]*hyr[4*j+2];
                    v.w = watt*hxr[4*j+3]*hyr[4*j+3];
                    *(float4*)&ctw[a*20 + 4*j] = v;
                }
                __syncwarp();
                {
                    int dd = a & 15, half = a >> 4;
                    float a0 = 0.f, a1 = 0.f, a2 = 0.f, a3 = 0.f;
                    #pragma unroll
                    for (int aa = 0; aa < 4; aa++) {
                        a0 += ctw[((aa     )*2 + half)*20 + dd];
                        a1 += ctw[((aa +  4)*2 + half)*20 + dd];
                        a2 += ctw[((aa +  8)*2 + half)*20 + dd];
                        a3 += ctw[((aa + 12)*2 + half)*20 + dd];
                    }
                    float acc = (a0 + a1) + (a2 + a3);
                    acc += __shfl_xor_sync(~0u, acc, 16);
                    if (a < 16)
                        sxu[ypar][wg*16 + a] = slg[a]*(acc - wcs) + slb[a];
                }
                GBAR();

                // FFN: 2 threads per output f
                {
                    int f = tf & 63, half = tf >> 6;
                    float sp;
                    if (l == 0 && half == 0) {
                        sp = fb0[f] + sfw0[f]*sxo[i*64];
                    } else {
                        const float* fw = &dyn[OFF_FW + f*132 + ((l && half) ? 64 : 0)];
                        const float4* v4 = (const float4*)(half ? sxu[ypar] : (sxo + i*64));
                        sp = (l && !half) ? fbs[(l-1)*64 + f] : 0.f;
                        #pragma unroll
                        for (int j = 0; j < 16; j++) {
                            float4 w = *(const float4*)&fw[4*j];
                            float4 xv = v4[j];
                            sp += w.x*xv.x + w.y*xv.y + w.z*xv.z + w.w*xv.w;
                        }
                    }
                    sfr[ypar][half][f] = sp;
                }
                GBAR();

                // LN over 64: fused (sum, sumsq) tree
                float yv = 0.f;
                if (tf < 64) {
                    yv = sfr[ypar][0][tf] + sfr[ypar][1][tf];
                    float w1 = yv, w2 = yv*yv;
                    #pragma unroll
                    for (int o = 16; o > 0; o >>= 1) {
                        w1 += __shfl_xor_sync(~0u, w1, o);
                        w2 += __shfl_xor_sync(~0u, w2, o);
                    }
                    if ((tf & 31) == 0) { sred[ypar][tf >> 5] = w1; sred2[ypar][tf >> 5] = w2; }
                }
                GBAR();
                if (tf < 64) {
                    float mean = (sred[ypar][0] + sred[ypar][1]) * (1.f/64.f);
                    float ms   = (sred2[ypar][0] + sred2[ypar][1]) * (1.f/64.f);
                    float var  = ms - mean*mean;
                    float dv = yv - mean;
                    float xn = dv * rsqrtf(var + EPSL) * fln_g[l*64 + tf] + fln_b[l*64 + tf];
                    g_x[cell*64 + tf] = xn;
                    minv = fminf(minv, xn);
                    if (y == x) { dval = xn; sawdiag = true; }
                    else offm = fmaxf(offm, xn);
                }
            } // y loop

            if (tf < 64) {
                atomicMax(&g_off_key[b*64 + tf], fkey(offm));
                if (sawdiag) atomicMax(&g_diag_key[b*64 + tf], fkey(dval));
                float w = minv;
                #pragma unroll
                for (int o = 16; o > 0; o >>= 1) w = fminf(w, __shfl_xor_sync(~0u, w, o));
                if ((tf & 31) == 0) atomicMin(&g_min_key, fkey(w));
            }
        }
        gsync();
    } // layers

    // ================= final =================
    if (blk == 0) {
        pool_finish2(LL - 1, opW, opb, dyn, pooled, psr, sstage);
        __syncthreads();
        if (t < 32) {
            float s0 = g_scores[t], s1 = g_scores[32 + t];
            float m = 0.5f*(s0 + s1);
            float v = 0.5f*((s0 - m)*(s0 - m) + (s1 - m)*(s1 - m));
            float r = rsqrtf(v + EPSL);
            out[t]      = (s0 - m)*r;
            out[32 + t] = (s1 - m)*r;
        }
    }
}

// ---------------- launch ----------------
extern "C" void kernel_launch(void* const* d_in, const int* in_sizes, int n_in,
                              void* d_out, int out_size) {
    const int*   ei    = (const int*)  d_in[0];
    const float* W0    = (const float*)d_in[2];
    const float* b0    = (const float*)d_in[3];
    const float* Ws    = (const float*)d_in[4];
    const float* bs    = (const float*)d_in[5];
    const float* ln_g  = (const float*)d_in[6];
    const float* ln_b  = (const float*)d_in[7];
    const float* fW0   = (const float*)d_in[8];
    const float* fb0   = (const float*)d_in[9];
    const float* fWs   = (const float*)d_in[10];
    const float* fbs   = (const float*)d_in[11];
    const float* fln_g = (const float*)d_in[12];
    const float* fln_b = (const float*)d_in[13];
    const float* opW   = (const float*)d_in[14];
    const float* opb   = (const float*)d_in[15];
    int E = in_sizes[0] / 2;

    cudaFuncSetAttribute(mega, cudaFuncAttributeMaxDynamicSharedMemorySize, DYNB);
    mega<<<GRID, TPB, DYNB>>>(ei, E, W0, b0, Ws, bs, ln_g, ln_b,
                              fW0, fb0, fWs, fbs, fln_g, fln_b,
                              opW, opb, (float*)d_out);
}

// round 8
// speedup vs baseline: 3.1865x; 1.0510x over previous
#include <cuda_runtime.h>
#include <cuda_bf16.h>
#include <cuda_pipeline.h>

#define BB   2
#define NN   32
#define LL   4
#define EPSL 1e-5f
#define CELLS 2048
#define GRID 256
#define TPB  256

// dynamic smem layout (floats)
#define OFF_CT 0        // 5120: contraction 8x640 | init sadj | h-tail W 64x68 | final pooled4
#define OFF_FW 5120     // FFN weights 64x140 = 8960
#define OFF_SY 14080    // 2 groups x 2 bufs x (32x68) = 8704
#define OFF_XA 22784    // x ping-pong: 2 bufs x 2 groups x 256 = 1024
#define DYNF   23808
#define DYNB   (DYNF*4)

// ---------------- device scratch ----------------
__device__ __align__(16) float g_hbuf[2][CELLS*64];
__device__ unsigned g_diag_key[LL*128];
__device__ unsigned g_off_key [LL*128];
__device__ unsigned g_min_key4[LL];
__device__ int g_cnt, g_gen;

__device__ __forceinline__ unsigned fkey(float f) {
    unsigned u = __float_as_uint(f);
    return (u & 0x80000000u) ? ~u : (u | 0x80000000u);
}
__device__ __forceinline__ float funkey(unsigned k) {
    unsigned u = (k & 0x80000000u) ? (k & 0x7fffffffu) : ~k;
    return __uint_as_float(u);
}

// ---- software grid barrier ----
__device__ __forceinline__ void gsync() {
    __syncthreads();
    if (threadIdx.x == 0) {
        __threadfence();
        int g = *(volatile int*)&g_gen;
        if (atomicAdd(&g_cnt, 1) == GRID - 1) {
            g_cnt = 0;
            __threadfence();
            atomicExch(&g_gen, g + 1);
        } else {
            while (*(volatile int*)&g_gen == g) {}
        }
        __threadfence();
    }
    __syncthreads();
}

#define GBAR() asm volatile("bar.sync %0, %1;" :: "r"(barid), "r"(128) : "memory")

// ---------------- megakernel ----------------
__global__ void __launch_bounds__(TPB, 2)
mega(const int* ei, int E,
     const float* W0, const float* b0, const float* Ws, const float* bs,
     const float* ln_g, const float* ln_b,
     const float* fW0, const float* fb0, const float* fWs, const float* fbs,
     const float* fln_g, const float* fln_b,
     const float* opW, const float* opb, float* out)
{
    extern __shared__ __align__(16) float dyn[];
    __shared__ __align__(16) float sxu[2][64];
    __shared__ float slg[16], slb[16];
    __shared__ float sred[2][4], sred2[2][4];
    __shared__ float sfw0[64];
    __shared__ float psum[256];
    __shared__ float psr[2];
    __shared__ int   sflag;

    int t   = threadIdx.x;
    int blk = blockIdx.x;
    int pair = blk >> 2;
    int b = pair >> 5, x = pair & 31;
    int y0 = (blk & 3) * 8;
    int ypar = t >> 7;                 // y-group 0/1
    int tf   = t & 127;
    int wrp  = tf >> 5;                // head / warp-in-group
    int la   = tf & 31;                // lane
    int barid = 1 + ypar;

    // ================= init: adjacency (per block) + h0 + keys =================
    {
        float* sadj = dyn + OFF_CT;    // 2048 floats
        if (t == 0) sflag = 0;
        __syncthreads();
        for (int i = t; i < 512; i += TPB)
            if (ei[2*i + 1] != 0) sflag = 1;     // int32 vs int64 detect
        for (int i = t; i < CELLS; i += TPB) sadj[i] = 0.f;
        __syncthreads();
        int stride = sflag ? 1 : 2;
        for (int e = t; e < E; e += TPB) {
            int e0 = ei[stride*e];
            int e1 = ei[stride*E + stride*e];
            int g  = e0 >> 5;
            int ls = e0 - (g << 5);
            int ld = e1 - (g << 5);
            if (g >= 0 && g < BB && ld >= 0 && ld < NN)
                atomicAdd(&sadj[(g << 10) + (ls << 5) + ld], 1.f);
        }
        __syncthreads();
        if (t < BB*NN) { int bb = t >> 5, n = t & 31; sadj[(bb << 10) + n*33] = 2.f; }
        __syncthreads();
        // h0 for own 8 cells
        for (int o = t; o < 512; o += TPB) {
            int yy = o >> 6, f = o & 63;
            float av = sadj[(b << 10) + (x << 5) + y0 + yy];
            g_hbuf[0][((b*32 + x)*32 + y0 + yy)*64 + f] = av*W0[f] + b0[f];
        }
        // x_old (layer 0) = adjacency scalar, into x-ping-pong buffer 0
        if (tf < 4)
            dyn[OFF_XA + ypar*256 + tf*64] = sadj[(b << 10) + (x << 5) + y0 + 2*tf + ypar];
        if (blk == 0) {
            for (int i = t; i < LL*128; i += TPB) { g_diag_key[i] = 0u; g_off_key[i] = 0u; }
            if (t < LL) g_min_key4[t] = 0xFFFFFFFFu;
        }
    }
    gsync();

    // ================= layers =================
    for (int l = 0; l < LL; l++) {
        const float* hcur = g_hbuf[l & 1];
        float* bufA = dyn + OFF_SY + ypar*4352;
        float* bufB = bufA + 2176;
        float* ctw  = dyn + OFF_CT + (ypar*4 + wrp)*640;
        float* sxo  = dyn + OFF_XA + (l & 1)*512 + ypar*256;
        float* sxn  = dyn + OFF_XA + ((l + 1) & 1)*512 + ypar*256;

        // ---- staging: FFN weights, x-slab, LN params ----
        if (l == 0) {
            for (int i = t; i < 4096; i += TPB) {
                int f = i >> 6, c = i & 63;
                dyn[OFF_FW + f*140 + 68 + c] = fW0[f*65 + 1 + c];
            }
            if (t < 64) sfw0[t] = fW0[t*65];
        } else {
            for (int i = t; i < 2048; i += TPB) {
                int f = i >> 5, u = i & 31;
                __pipeline_memcpy_async(&dyn[OFF_FW + f*140 + u*4 + (u >= 16 ? 4 : 0)],
                                        fWs + (l-1)*8192 + f*128 + u*4, 16);
            }
        }
        {
            const float* xb = hcur + ((b*32 + x)*32)*64;
            for (int v = tf; v < 512; v += 128)
                __pipeline_memcpy_async(&bufA[(v >> 4)*68 + (v & 15)*4], xb + v*4, 16);
        }
        if (t < 16) { slg[t] = ln_g[l*16 + t]; slb[t] = ln_b[l*16 + t]; }
        __pipeline_commit();
        __pipeline_wait_prior(0);
        __syncthreads();

        // ---- x-side registers: hxr + folded q constants ----
        float hxr[16], gq[16];
        float A = 0.f, Bc = 0.f;
        {
            #pragma unroll
            for (int j = 0; j < 4; j++) {
                float4 v = *(const float4*)&bufA[la*68 + wrp*16 + 4*j];
                hxr[4*j] = v.x; hxr[4*j+1] = v.y; hxr[4*j+2] = v.z; hxr[4*j+3] = v.w;
            }
            float s0 = 0.f, s1 = 0.f;
            #pragma unroll
            for (int d = 0; d < 16; d++) { s0 += hxr[d]; s1 += hxr[d]*hxr[d]; }
            float mn = s0 * (1.f/16.f);
            float rstd = rsqrtf(s1*(1.f/16.f) - mn*mn + EPSL);
            #pragma unroll
            for (int d = 0; d < 16; d++) {
                float qx = (hxr[d] - mn)*rstd*slg[d] + slb[d];
                gq[d] = qx * slg[d];
                A  += gq[d];
                Bc += qx * slb[d];
            }
        }

        const float* hyb = hcur + b*65536;     // + a*2048 + y*64
        {   // prefetch iter-0 y-slab into bufB
            int y = y0 + ypar;
            for (int v = tf; v < 512; v += 128)
                __pipeline_memcpy_async(&bufB[(v >> 4)*68 + (v & 15)*4],
                                        hyb + (v >> 4)*2048 + y*64 + (v & 15)*4, 16);
            __pipeline_commit();
        }

        float offm = -3.0e38f, minv = 3.0e38f, dval = -3.0e38f;
        bool sawdiag = false;
        int ffn_f = wrp*16 + (la >> 1);
        int half  = la & 1;

        for (int i = 0; i < 4; i++) {
            int y = y0 + 2*i + ypar;
            float* cur = (i & 1) ? bufA : bufB;
            float* nxt = (i & 1) ? bufB : bufA;

            __pipeline_wait_prior(0);
            GBAR();                            // slab visible; sxu/sred reuse safe

            float hyr[16];
            #pragma unroll
            for (int j = 0; j < 4; j++) {
                float4 v = *(const float4*)&cur[la*68 + wrp*16 + 4*j];
                hyr[4*j] = v.x; hyr[4*j+1] = v.y; hyr[4*j+2] = v.z; hyr[4*j+3] = v.w;
            }
            if (i < 3) {                       // prefetch next y
                int yn = y + 2;
                for (int v = tf; v < 512; v += 128)
                    __pipeline_memcpy_async(&nxt[(v >> 4)*68 + (v & 15)*4],
                                            hyb + (v >> 4)*2048 + yn*64 + (v & 15)*4, 16);
                __pipeline_commit();
            }

            // stats (register dots)
            float s0 = 0.f, s1 = 0.f, dg = 0.f, mprod = 0.f, eprod = 0.f;
            #pragma unroll
            for (int d = 0; d < 16; d++) {
                s0 += hyr[d];
                s1 += hyr[d]*hyr[d];
                dg += gq[d]*hyr[d];
                float pr = hxr[d]*hyr[d];
                mprod += pr;
                eprod += pr*pr;
            }
            float mny = s0 * (1.f/16.f);
            float rsy = rsqrtf(s1*(1.f/16.f) - mny*mny + EPSL);
            float s = (rsy*(dg - mny*A) + Bc) * 0.25f;
            float mm = mprod * (1.f/16.f);
            float rstd = rsqrtf(eprod*(1.f/16.f) - mm*mm + EPSL);

            // softmax over a = warp lanes (LN-bounded scores; no max-subtract)
            float ex = __expf(s);
            float t2 = ex, t3 = ex * mm * rstd;
            #pragma unroll
            for (int o = 16; o > 0; o >>= 1) {
                t2 += __shfl_xor_sync(~0u, t2, o);
                t3 += __shfl_xor_sync(~0u, t3, o);
            }
            float inv = 1.f / t2;
            float watt = ex * rstd * inv;
            float wcs  = t3 * inv;

            // contraction: warp-private smem transpose
            #pragma unroll
            for (int j = 0; j < 4; j++) {
                float4 v;
                v.x = watt*hxr[4*j  ]*hyr[4*j  ];
                v.y = watt*hxr[4*j+1]*hyr[4*j+1];
                v.z = watt*hxr[4*j+2]*hyr[4*j+2];
                v.w = watt*hxr[4*j+3]*hyr[4*j+3];
                *(float4*)&ctw[la*20 + 4*j] = v;
            }
            __syncwarp();
            {
                int dd = la & 15, hh = la >> 4;
                float a0 = 0.f, a1 = 0.f, a2 = 0.f, a3 = 0.f;
                #pragma unroll
                for (int aa = 0; aa < 4; aa++) {
                    a0 += ctw[((aa     )*2 + hh)*20 + dd];
                    a1 += ctw[((aa +  4)*2 + hh)*20 + dd];
                    a2 += ctw[((aa +  8)*2 + hh)*20 + dd];
                    a3 += ctw[((aa + 12)*2 + hh)*20 + dd];
                }
                float acc = (a0 + a1) + (a2 + a3);
                acc += __shfl_xor_sync(~0u, acc, 16);
                if (la < 16)
                    sxu[ypar][wrp*16 + la] = slg[la]*(acc - wcs) + slb[la];
            }
            GBAR();

            // FFN: lane-pair halves of concat([x_old, xu]), combine via shfl
            float sp;
            if (l == 0 && half == 0) {
                sp = fb0[ffn_f] + sfw0[ffn_f]*sxo[i*64];
            } else {
                const float* fw = &dyn[OFF_FW + ffn_f*140 + (half ? 68 : 0)];
                const float4* v4 = (const float4*)(half ? sxu[ypar] : (sxo + i*64));
                sp = half ? 0.f : fbs[(l-1)*64 + ffn_f];
                #pragma unroll
                for (int j = 0; j < 16; j++) {
                    float4 w = *(const float4*)&fw[4*j];
                    float4 xv = v4[j];
                    sp += w.x*xv.x + w.y*xv.y + w.z*xv.z + w.w*xv.w;
                }
            }
            sp += __shfl_xor_sync(~0u, sp, 1);   // yv for ffn_f, both lanes

            // LN over 64 (each f duplicated x2 -> /128)
            float w1 = sp, w2 = sp*sp;
            #pragma unroll
            for (int o = 16; o > 0; o >>= 1) {
                w1 += __shfl_xor_sync(~0u, w1, o);
                w2 += __shfl_xor_sync(~0u, w2, o);
            }
            if (la == 0) { sred[ypar][wrp] = w1; sred2[ypar][wrp] = w2; }
            GBAR();
            {
                float mean = (sred[ypar][0] + sred[ypar][1] + sred[ypar][2] + sred[ypar][3]) * (1.f/128.f);
                float ms   = (sred2[ypar][0] + sred2[ypar][1] + sred2[ypar][2] + sred2[ypar][3]) * (1.f/128.f);
                float var  = ms - mean*mean;
                float dv = sp - mean;
                float xn = dv * rsqrtf(var + EPSL) * fln_g[l*64 + ffn_f] + fln_b[l*64 + ffn_f];
                if (half == 0) {
                    sxn[i*64 + ffn_f] = xn;
                    minv = fminf(minv, xn);
                    if (y == x) { dval = xn; sawdiag = true; }
                    else offm = fmaxf(offm, xn);
                }
            }
        } // y loop

        // pooling atomics (per-layer keys; half0 threads own distinct f)
        if (half == 0) {
            atomicMax(&g_off_key[l*128 + b*64 + ffn_f], fkey(offm));
            if (sawdiag) atomicMax(&g_diag_key[l*128 + b*64 + ffn_f], fkey(dval));
        }
        {
            float w = minv;
            #pragma unroll
            for (int o = 16; o > 0; o >>= 1) w = fminf(w, __shfl_xor_sync(~0u, w, o));
            if (la == 0) atomicMin(&g_min_key4[l], fkey(w));
        }

        // ---- h-tail: next-layer h for own 8 cells ----
        if (l < LL - 1) {
            __syncthreads();                   // both groups done with ctw/slabs
            for (int i2 = t; i2 < 1024; i2 += TPB) {
                int f = i2 >> 4, u = i2 & 15;
                __pipeline_memcpy_async(&dyn[OFF_CT + f*68 + u*4],
                                        Ws + l*4096 + f*64 + u*4, 16);
            }
            __pipeline_commit();
            __pipeline_wait_prior(0);
            __syncthreads();
            int f = t & 63, yyA = t >> 6, yyB = yyA + 4;
            const float4* wrow = (const float4*)&dyn[OFF_CT + f*68];
            const float4* xA = (const float4*)&dyn[OFF_XA + ((l+1)&1)*512 + (yyA & 1)*256 + (yyA >> 1)*64];
            const float4* xB = (const float4*)&dyn[OFF_XA + ((l+1)&1)*512 + (yyB & 1)*256 + (yyB >> 1)*64];
            float accA = bs[l*64 + f], accB = accA;
            #pragma unroll
            for (int j = 0; j < 16; j++) {
                float4 w = wrow[j], va = xA[j], vb = xB[j];
                accA += w.x*va.x + w.y*va.y + w.z*va.z + w.w*va.w;
                accB += w.x*vb.x + w.y*vb.y + w.z*vb.z + w.w*vb.w;
            }
            float* hn = g_hbuf[(l+1) & 1];
            hn[((b*32 + x)*32 + y0 + yyA)*64 + f] = accA;
            hn[((b*32 + x)*32 + y0 + yyB)*64 + f] = accB;
        }
        gsync();
    } // layers

    // ================= final: all pool_finish + BN (block 0) =================
    if (blk == 0) {
        float* pooled4 = dyn + OFF_CT;         // 4 x 256
        for (int l2 = 0; l2 < LL; l2++) {
            float d0 = 0.f, d1 = 0.f, o0 = 0.f, o1 = 0.f, gmin = 0.f;
            if (t < 64) {
                d0 = funkey(g_diag_key[l2*128 + t]);
                d1 = funkey(g_diag_key[l2*128 + 64 + t]);
                o0 = funkey(g_off_key [l2*128 + t]);
                o1 = funkey(g_off_key [l2*128 + 64 + t]);
                gmin = funkey(g_min_key4[l2]);
                float m = fmaxf(d0, d1);
                #pragma unroll
                for (int o = 16; o > 0; o >>= 1) m = fmaxf(m, __shfl_xor_sync(~0u, m, o));
                if ((t & 31) == 0) psr[t >> 5] = m;
            }
            __syncthreads();
            if (t < 64) {
                float gdm = fmaxf(psr[0], psr[1]);
                float val = fabsf(gdm - gmin);
                pooled4[l2*256 + t]       = d0;
                pooled4[l2*256 + 64 + t]  = fmaxf(o0, d0 - val);
                pooled4[l2*256 + 128 + t] = d1;
                pooled4[l2*256 + 192 + t] = fmaxf(o1, d1 - val);
            }
            __syncthreads();
        }
        // parallel dot: t -> (l2, bq, j)
        {
            int l2 = t >> 6, bq = (t >> 5) & 1, j = t & 31;
            const float4* w4 = (const float4*)(opW + l2*4096 + j*128);
            const float4* p4 = (const float4*)&pooled4[l2*256 + bq*128];
            float acc = opb[l2*32 + j];
            #pragma unroll
            for (int k = 0; k < 32; k++) {
                float4 w = w4[k], p = p4[k];
                acc += w.x*p.x + w.y*p.y + w.z*p.z + w.w*p.w;
            }
            psum[t] = acc;
        }
        __syncthreads();
        if (t < 32) {
            float s0 = psum[t]      + psum[64 + t]      + psum[128 + t]      + psum[192 + t];
            float s1 = psum[32 + t] + psum[96 + t]      + psum[160 + t]      + psum[224 + t];
            float m = 0.5f*(s0 + s1);
            float v = 0.5f*((s0 - m)*(s0 - m) + (s1 - m)*(s1 - m));
            float r = rsqrtf(v + EPSL);
            out[t]      = (s0 - m)*r;
            out[32 + t] = (s1 - m)*r;
        }
    }
}

// ---------------- launch ----------------
extern "C" void kernel_launch(void* const* d_in, const int* in_sizes, int n_in,
                              void* d_out, int out_size) {
    const int*   ei    = (const int*)  d_in[0];
    const float* W0    = (const float*)d_in[2];
    const float* b0    = (const float*)d_in[3];
    const float* Ws    = (const float*)d_in[4];
    const float* bs    = (const float*)d_in[5];
    const float* ln_g  = (const float*)d_in[6];
    const float* ln_b  = (const float*)d_in[7];
    const float* fW0   = (const float*)d_in[8];
    const float* fb0   = (const float*)d_in[9];
    const float* fWs   = (const float*)d_in[10];
    const float* fbs   = (const float*)d_in[11];
    const float* fln_g = (const float*)d_in[12];
    const float* fln_b = (const float*)d_in[13];
    const float* opW   = (const float*)d_in[14];
    const float* opb   = (const float*)d_in[15];
    int E = in_sizes[0] / 2;

    cudaFuncSetAttribute(mega, cudaFuncAttributeMaxDynamicSharedMemorySize, DYNB);
    mega<<<GRID, TPB, DYNB>>>(ei, E, W0, b0, Ws, bs, ln_g, ln_b,
                              fW0, fb0, fWs, fbs, fln_g, fln_b,
                              opW, opb, (float*)d_out);
}

// round 9
// speedup vs baseline: 3.2021x; 1.0049x over previous
#include <cuda_runtime.h>
#include <cuda_bf16.h>
#include <cuda_pipeline.h>

#define BB   2
#define NN   32
#define LL   4
#define EPSL 1e-5f
#define GRID 256
#define TPB  256

// dynamic smem layout (floats)
#define OFF_CT  0       // 5120: contraction 8x640 | final pooled4
#define OFF_FW  5120    // 8960: FFN weights 64x140
#define OFF_SY  14080   // 8704: slabs (l>=1) | layer-0 h-tail W (64x68)
#define OFF_XA  22784   // 1024: x ping-pong 2 x 2 x 256
#define OFF_ADJ 23808   // 4352: adj(2048)+adjT(2048) in l0, then h-tail W (l>=1)
#define DYNF    28160
#define DYNB    (DYNF*4)

// ---------------- device scratch ----------------
__device__ __align__(16) float g_hbuf[2][2048*64];
__device__ unsigned g_diag_key[LL*128];        // static zero-init; reset at run end
__device__ unsigned g_off_key [LL*128];
__device__ unsigned g_min_key4[LL] = {0xFFFFFFFFu,0xFFFFFFFFu,0xFFFFFFFFu,0xFFFFFFFFu};
__device__ int g_cnt, g_gen;

__device__ __forceinline__ unsigned fkey(float f) {
    unsigned u = __float_as_uint(f);
    return (u & 0x80000000u) ? ~u : (u | 0x80000000u);
}
__device__ __forceinline__ float funkey(unsigned k) {
    unsigned u = (k & 0x80000000u) ? (k & 0x7fffffffu) : ~k;
    return __uint_as_float(u);
}

// ---- software grid barrier ----
__device__ __forceinline__ void gsync() {
    __syncthreads();
    if (threadIdx.x == 0) {
        __threadfence();
        int g = *(volatile int*)&g_gen;
        if (atomicAdd(&g_cnt, 1) == GRID - 1) {
            g_cnt = 0;
            __threadfence();
            atomicExch(&g_gen, g + 1);
        } else {
            while (*(volatile int*)&g_gen == g) {}
        }
        __threadfence();
    }
    __syncthreads();
}

#define GBAR() asm volatile("bar.sync %0, %1;" :: "r"(barid), "r"(128) : "memory")

// ---------------- megakernel ----------------
__global__ void __launch_bounds__(TPB, 2)
mega(const int* ei, int E,
     const float* W0, const float* b0, const float* Ws, const float* bs,
     const float* ln_g, const float* ln_b,
     const float* fW0, const float* fb0, const float* fWs, const float* fbs,
     const float* fln_g, const float* fln_b,
     const float* opW, const float* opb, float* out)
{
    extern __shared__ __align__(16) float dyn[];
    __shared__ __align__(16) float sxu[2][64];
    __shared__ float slg[16], slb[16];
    __shared__ float sred[2][2][4], sred2[2][2][4];
    __shared__ float sfw0[64], sw0[64], sb0[64];
    __shared__ float psum[256];
    __shared__ float psr[2];
    __shared__ int   sflag;

    int t   = threadIdx.x;
    int blk = blockIdx.x;
    int pair = blk >> 2;
    int b = pair >> 5, x = pair & 31;
    int y0 = (blk & 3) * 8;
    int ypar = t >> 7, tf = t & 127, wrp = tf >> 5, la = tf & 31;
    int barid = 1 + ypar;

    float* sadj  = dyn + OFF_ADJ;          // adj  (b,a,y)
    float* sadjT = dyn + OFF_ADJ + 2048;   // adjT (b,y,a)

    // ================= init: adjacency per block (no gsync needed) =================
    {
        if (t == 0) sflag = 0;
        __syncthreads();
        for (int i = t; i < 512; i += TPB)
            if (ei[2*i + 1] != 0) sflag = 1;     // int32 vs int64 detect
        for (int i = t; i < 2048; i += TPB) sadj[i] = 0.f;
        if (t < 64) { sw0[t] = W0[t]; sb0[t] = b0[t]; }
        __syncthreads();
        int stride = sflag ? 1 : 2;
        for (int e = t; e < E; e += TPB) {
            int e0 = ei[stride*e];
            int e1 = ei[stride*E + stride*e];
            int g  = e0 >> 5;
            int ls = e0 - (g << 5);
            int ld = e1 - (g << 5);
            if (g >= 0 && g < BB && ld >= 0 && ld < NN)
                atomicAdd(&sadj[(g << 10) + (ls << 5) + ld], 1.f);
        }
        __syncthreads();
        if (t < 64) { int bb = t >> 5, n = t & 31; sadj[(bb << 10) + n*33] = 2.f; }
        __syncthreads();
        for (int i = t; i < 2048; i += TPB) {
            int bb = i >> 10, aa = (i >> 5) & 31, yy = i & 31;
            sadjT[(bb << 10) + (yy << 5) + aa] = sadj[i];
        }
        if (tf < 4)
            dyn[OFF_XA + ypar*256 + tf*64] = sadj[(b << 10) + (x << 5) + y0 + 2*tf + ypar];
        __syncthreads();
    }

    // ================= layers =================
    for (int l = 0; l < LL; l++) {
        const float* hcur = g_hbuf[l & 1];
        float* bufA = dyn + OFF_SY + ypar*4352;
        float* bufB = bufA + 2176;
        float* ctw  = dyn + OFF_CT + (ypar*4 + wrp)*640;
        float* sxo  = dyn + OFF_XA + (l & 1)*512 + ypar*256;
        float* sxn  = dyn + OFF_XA + ((l + 1) & 1)*512 + ypar*256;
        int ffn_f = wrp*16 + (la >> 1);
        int half  = la & 1;

        // ---- staging ----
        if (l == 0) {
            for (int i = t; i < 4096; i += TPB)
                dyn[OFF_FW + (i >> 6)*140 + 68 + (i & 63)] = fW0[(i >> 6)*65 + 1 + (i & 63)];
            if (t < 64) sfw0[t] = fW0[t*65];
            // prefetch Ws[0] (h-tail) into idle slab region; waited at h-tail only
            for (int i2 = t; i2 < 1024; i2 += TPB)
                __pipeline_memcpy_async(&dyn[OFF_SY + (i2 >> 4)*68 + (i2 & 15)*4],
                                        Ws + i2*4, 16);
            __pipeline_commit();
        } else {
            for (int i = t; i < 2048; i += TPB) {
                int f = i >> 5, u = i & 31;
                __pipeline_memcpy_async(&dyn[OFF_FW + f*140 + u*4 + (u >= 16 ? 4 : 0)],
                                        fWs + (l-1)*8192 + f*128 + u*4, 16);
            }
            const float* xb = hcur + ((b*32 + x)*32)*64;
            for (int v = tf; v < 512; v += 128)
                __pipeline_memcpy_async(&bufA[(v >> 4)*68 + (v & 15)*4], xb + v*4, 16);
            __pipeline_commit();
        }
        if (t < 16) { slg[t] = ln_g[l*16 + t]; slb[t] = ln_b[l*16 + t]; }
        float flg = fln_g[l*64 + ffn_f], flb = fln_b[l*64 + ffn_f];
        float fbias = (l == 0) ? fb0[ffn_f] : fbs[(l-1)*64 + ffn_f];
        if (l > 0) __pipeline_wait_prior(0);
        __syncthreads();

        // ---- x-side registers + folded q constants ----
        float hxr[16], gq[16];
        float A = 0.f, Bc = 0.f;
        {
            if (l == 0) {
                float adjx = sadj[(b << 10) + (x << 5) + la];
                #pragma unroll
                for (int d = 0; d < 16; d++)
                    hxr[d] = adjx*sw0[wrp*16 + d] + sb0[wrp*16 + d];
            } else {
                #pragma unroll
                for (int j = 0; j < 4; j++) {
                    float4 v = *(const float4*)&bufA[la*68 + wrp*16 + 4*j];
                    hxr[4*j] = v.x; hxr[4*j+1] = v.y; hxr[4*j+2] = v.z; hxr[4*j+3] = v.w;
                }
            }
            float s0 = 0.f, s1 = 0.f;
            #pragma unroll
            for (int d = 0; d < 16; d++) { s0 += hxr[d]; s1 += hxr[d]*hxr[d]; }
            float mn = s0 * (1.f/16.f);
            float rstd = rsqrtf(s1*(1.f/16.f) - mn*mn + EPSL);
            #pragma unroll
            for (int d = 0; d < 16; d++) {
                float qx = (hxr[d] - mn)*rstd*slg[d] + slb[d];
                gq[d] = qx * slg[d];
                A  += gq[d];
                Bc += qx * slb[d];
            }
        }

        const float* hyb = hcur + b*65536;
        if (l > 0) {   // prefetch iter-0 y-slab
            int y = y0 + ypar;
            for (int v = tf; v < 512; v += 128)
                __pipeline_memcpy_async(&bufB[(v >> 4)*68 + (v & 15)*4],
                                        hyb + (v >> 4)*2048 + y*64 + (v & 15)*4, 16);
            __pipeline_commit();
        }

        float offm = -3.0e38f, minv = 3.0e38f, dval = -3.0e38f;
        bool sawdiag = false;
        float sp_prev = 0.f;

        for (int i = 0; i < 4; i++) {
            int y = y0 + 2*i + ypar;
            if (l > 0) __pipeline_wait_prior(0);
            GBAR();                            // slab ready; sred[i-1] ready

            // ---- deferred epilogue of iter i-1 ----
            if (i > 0) {
                int pj = i - 1, pb = pj & 1;
                int yprev = y0 + 2*pj + ypar;
                float mean = (sred[ypar][pb][0] + sred[ypar][pb][1] +
                              sred[ypar][pb][2] + sred[ypar][pb][3]) * (1.f/128.f);
                float ms   = (sred2[ypar][pb][0] + sred2[ypar][pb][1] +
                              sred2[ypar][pb][2] + sred2[ypar][pb][3]) * (1.f/128.f);
                float xn = (sp_prev - mean)*rsqrtf(ms - mean*mean + EPSL)*flg + flb;
                if (half == 0) {
                    sxn[pj*64 + ffn_f] = xn;
                    minv = fminf(minv, xn);
                    if (yprev == x) { dval = xn; sawdiag = true; }
                    else offm = fmaxf(offm, xn);
                }
            }

            // ---- y-side registers ----
            float hyr[16];
            if (l == 0) {
                float adjy = sadjT[(b << 10) + (y << 5) + la];
                #pragma unroll
                for (int d = 0; d < 16; d++)
                    hyr[d] = adjy*sw0[wrp*16 + d] + sb0[wrp*16 + d];
            } else {
                float* cur = (i & 1) ? bufA : bufB;
                #pragma unroll
                for (int j = 0; j < 4; j++) {
                    float4 v = *(const float4*)&cur[la*68 + wrp*16 + 4*j];
                    hyr[4*j] = v.x; hyr[4*j+1] = v.y; hyr[4*j+2] = v.z; hyr[4*j+3] = v.w;
                }
                if (i < 3) {
                    float* nxt = (i & 1) ? bufB : bufA;
                    int yn = y + 2;
                    for (int v = tf; v < 512; v += 128)
                        __pipeline_memcpy_async(&nxt[(v >> 4)*68 + (v & 15)*4],
                                                hyb + (v >> 4)*2048 + yn*64 + (v & 15)*4, 16);
                    __pipeline_commit();
                }
            }

            // ---- stats ----
            float s0 = 0.f, s1 = 0.f, dg = 0.f, mprod = 0.f, eprod = 0.f;
            #pragma unroll
            for (int d = 0; d < 16; d++) {
                s0 += hyr[d];
                s1 += hyr[d]*hyr[d];
                dg += gq[d]*hyr[d];
                float pr = hxr[d]*hyr[d];
                mprod += pr;
                eprod += pr*pr;
            }
            float mny = s0 * (1.f/16.f);
            float rsy = rsqrtf(s1*(1.f/16.f) - mny*mny + EPSL);
            float s = (rsy*(dg - mny*A) + Bc) * 0.25f;
            float mm = mprod * (1.f/16.f);
            float rstd = rsqrtf(eprod*(1.f/16.f) - mm*mm + EPSL);

            // ---- softmax over a = warp lanes ----
            float ex = __expf(s);
            float t2 = ex, t3 = ex * mm * rstd;
            #pragma unroll
            for (int o = 16; o > 0; o >>= 1) {
                t2 += __shfl_xor_sync(~0u, t2, o);
                t3 += __shfl_xor_sync(~0u, t3, o);
            }
            float inv = 1.f / t2;
            float watt = ex * rstd * inv;
            float wcs  = t3 * inv;

            // ---- contraction: warp-private smem transpose ----
            #pragma unroll
            for (int j = 0; j < 4; j++) {
                float4 v;
                v.x = watt*hxr[4*j  ]*hyr[4*j  ];
                v.y = watt*hxr[4*j+1]*hyr[4*j+1];
                v.z = watt*hxr[4*j+2]*hyr[4*j+2];
                v.w = watt*hxr[4*j+3]*hyr[4*j+3];
                *(float4*)&ctw[la*20 + 4*j] = v;
            }
            __syncwarp();
            {
                int dd = la & 15, hh = la >> 4;
                float a0 = 0.f, a1 = 0.f, a2 = 0.f, a3 = 0.f;
                #pragma unroll
                for (int aa = 0; aa < 4; aa++) {
                    a0 += ctw[((aa     )*2 + hh)*20 + dd];
                    a1 += ctw[((aa +  4)*2 + hh)*20 + dd];
                    a2 += ctw[((aa +  8)*2 + hh)*20 + dd];
                    a3 += ctw[((aa + 12)*2 + hh)*20 + dd];
                }
                float acc = (a0 + a1) + (a2 + a3);
                acc += __shfl_xor_sync(~0u, acc, 16);
                if (la < 16)
                    sxu[ypar][wrp*16 + la] = slg[la]*(acc - wcs) + slb[la];
            }
            GBAR();

            // ---- FFN: lane-pair halves of concat([x_old, xu]) ----
            float sp;
            if (l == 0 && half == 0) {
                sp = fbias + sfw0[ffn_f]*sxo[i*64];
            } else {
                const float* fw = &dyn[OFF_FW + ffn_f*140 + (half ? 68 : 0)];
                const float4* v4 = (const float4*)(half ? sxu[ypar] : (sxo + i*64));
                sp = half ? 0.f : fbias;
                #pragma unroll
                for (int j = 0; j < 16; j++) {
                    float4 w = *(const float4*)&fw[4*j];
                    float4 xv = v4[j];
                    sp += w.x*xv.x + w.y*xv.y + w.z*xv.z + w.w*xv.w;
                }
            }
            sp += __shfl_xor_sync(~0u, sp, 1);

            // ---- LN reduction trees; epilogue deferred to next iter ----
            float w1 = sp, w2 = sp*sp;
            #pragma unroll
            for (int o = 16; o > 0; o >>= 1) {
                w1 += __shfl_xor_sync(~0u, w1, o);
                w2 += __shfl_xor_sync(~0u, w2, o);
            }
            if (la == 0) { sred[ypar][i & 1][wrp] = w1; sred2[ypar][i & 1][wrp] = w2; }
            sp_prev = sp;
        } // y loop

        GBAR();
        {   // deferred epilogue of iter 3
            float mean = (sred[ypar][1][0] + sred[ypar][1][1] +
                          sred[ypar][1][2] + sred[ypar][1][3]) * (1.f/128.f);
            float ms   = (sred2[ypar][1][0] + sred2[ypar][1][1] +
                          sred2[ypar][1][2] + sred2[ypar][1][3]) * (1.f/128.f);
            float xn = (sp_prev - mean)*rsqrtf(ms - mean*mean + EPSL)*flg + flb;
            int ylast = y0 + 6 + ypar;
            if (half == 0) {
                sxn[3*64 + ffn_f] = xn;
                minv = fminf(minv, xn);
                if (ylast == x) { dval = xn; sawdiag = true; }
                else offm = fmaxf(offm, xn);
            }
        }

        // ---- pooling atomics (per-layer keys) ----
        if (half == 0) {
            atomicMax(&g_off_key[l*128 + b*64 + ffn_f], fkey(offm));
            if (sawdiag) atomicMax(&g_diag_key[l*128 + b*64 + ffn_f], fkey(dval));
        }
        {
            float w = minv;
            #pragma unroll
            for (int o = 16; o > 0; o >>= 1) w = fminf(w, __shfl_xor_sync(~0u, w, o));
            if (la == 0) atomicMin(&g_min_key4[l], fkey(w));
        }

        // ---- prefetch h-tail W for l>=1 into dead adjacency region ----
        if (l >= 1 && l < LL - 1) {
            for (int v = tf; v < 512; v += 128) {
                int f = ypar*32 + (v >> 4), u = v & 15;
                __pipeline_memcpy_async(&dyn[OFF_ADJ + f*68 + u*4],
                                        Ws + l*4096 + f*64 + u*4, 16);
            }
            __pipeline_commit();
        }

        // ---- h-tail: next-layer h for own 8 cells ----
        if (l < LL - 1) {
            __pipeline_wait_prior(0);
            __syncthreads();
            const float* wbase = (l == 0) ? (dyn + OFF_SY) : (dyn + OFF_ADJ);
            int f = t & 63, yyA = t >> 6, yyB = yyA + 4;
            const float4* wrow = (const float4*)&wbase[f*68];
            const float4* xA = (const float4*)&dyn[OFF_XA + ((l+1)&1)*512 + (yyA & 1)*256 + (yyA >> 1)*64];
            const float4* xB = (const float4*)&dyn[OFF_XA + ((l+1)&1)*512 + (yyB & 1)*256 + (yyB >> 1)*64];
            float accA = bs[l*64 + f], accB = accA;
            #pragma unroll
            for (int j = 0; j < 16; j++) {
                float4 w = wrow[j], va = xA[j], vb = xB[j];
                accA += w.x*va.x + w.y*va.y + w.z*va.z + w.w*va.w;
                accB += w.x*vb.x + w.y*vb.y + w.z*vb.z + w.w*vb.w;
            }
            float* hn = g_hbuf[(l+1) & 1];
            hn[((b*32 + x)*32 + y0 + yyA)*64 + f] = accA;
            hn[((b*32 + x)*32 + y0 + yyB)*64 + f] = accB;
        }
        gsync();
    } // layers

    // ================= final: pool_finish all layers + BN (block 0) =================
    if (blk == 0) {
        float* pooled4 = dyn + OFF_CT;         // 4 x 256
        for (int l2 = 0; l2 < LL; l2++) {
            float d0 = 0.f, d1 = 0.f, o0 = 0.f, o1 = 0.f, gmin = 0.f;
            if (t < 64) {
                d0 = funkey(g_diag_key[l2*128 + t]);
                d1 = funkey(g_diag_key[l2*128 + 64 + t]);
                o0 = funkey(g_off_key [l2*128 + t]);
                o1 = funkey(g_off_key [l2*128 + 64 + t]);
                gmin = funkey(g_min_key4[l2]);
                float m = fmaxf(d0, d1);
                #pragma unroll
                for (int o = 16; o > 0; o >>= 1) m = fmaxf(m, __shfl_xor_sync(~0u, m, o));
                if ((t & 31) == 0) psr[t >> 5] = m;
            }
            __syncthreads();
            if (t < 64) {
                float gdm = fmaxf(psr[0], psr[1]);
                float val = fabsf(gdm - gmin);
                pooled4[l2*256 + t]       = d0;
                pooled4[l2*256 + 64 + t]  = fmaxf(o0, d0 - val);
                pooled4[l2*256 + 128 + t] = d1;
                pooled4[l2*256 + 192 + t] = fmaxf(o1, d1 - val);
            }
            __syncthreads();
        }
        {
            int l2 = t >> 6, bq = (t >> 5) & 1, j = t & 31;
            const float4* w4 = (const float4*)(opW + l2*4096 + j*128);
            const float4* p4 = (const float4*)&pooled4[l2*256 + bq*128];
            float acc = opb[l2*32 + j];
            #pragma unroll
            for (int k = 0; k < 32; k++) {
                float4 w = w4[k], p = p4[k];
                acc += w.x*p.x + w.y*p.y + w.z*p.z + w.w*p.w;
            }
            psum[t] = acc;
        }
        __syncthreads();
        if (t < 32) {
            float s0 = psum[t]      + psum[64 + t] + psum[128 + t] + psum[192 + t];
            float s1 = psum[32 + t] + psum[96 + t] + psum[160 + t] + psum[224 + t];
            float m = 0.5f*(s0 + s1);
            float v = 0.5f*((s0 - m)*(s0 - m) + (s1 - m)*(s1 - m));
            float r = rsqrtf(v + EPSL);
            out[t]      = (s0 - m)*r;
            out[32 + t] = (s1 - m)*r;
        }
        // reset keys for next graph replay (deterministic across runs)
        __syncthreads();
        for (int i = t; i < LL*128; i += TPB) { g_diag_key[i] = 0u; g_off_key[i] = 0u; }
        if (t < LL) g_min_key4[t] = 0xFFFFFFFFu;
    }
}

// ---------------- launch ----------------
extern "C" void kernel_launch(void* const* d_in, const int* in_sizes, int n_in,
                              void* d_out, int out_size) {
    const int*   ei    = (const int*)  d_in[0];
    const float* W0    = (const float*)d_in[2];
    const float* b0    = (const float*)d_in[3];
    const float* Ws    = (const float*)d_in[4];
    const float* bs    = (const float*)d_in[5];
    const float* ln_g  = (const float*)d_in[6];
    const float* ln_b  = (const float*)d_in[7];
    const float* fW0   = (const float*)d_in[8];
    const float* fb0   = (const float*)d_in[9];
    const float* fWs   = (const float*)d_in[10];
    const float* fbs   = (const float*)d_in[11];
    const float* fln_g = (const float*)d_in[12];
    const float* fln_b = (const float*)d_in[13];
    const float* opW   = (const float*)d_in[14];
    const float* opb   = (const float*)d_in[15];
    int E = in_sizes[0] / 2;

    cudaFuncSetAttribute(mega, cudaFuncAttributeMaxDynamicSharedMemorySize, DYNB);
    mega<<<GRID, TPB, DYNB>>>(ei, E, W0, b0, Ws, bs, ln_g, ln_b,
                              fW0, fb0, fWs, fbs, fln_g, fln_b,
                              opW, opb, (float*)d_out);
}

// round 11
// speedup vs baseline: 3.5516x; 1.1091x over previous
#include <cuda_runtime.h>
#include <cuda_bf16.h>
#include <cuda_pipeline.h>

#define BB   2
#define NN   32
#define LL   4
#define EPSL 1e-5f
#define GRID 256
#define TPB  256

// dynamic smem layout (floats)
#define OFF_CT  0       // 5120: contraction 8x640 | final pooled4
#define OFF_FW  5120    // 8960: FFN weights 64x140 | final psum
#define OFF_SY  14080   // 8704: slabs (l>=1) | l0: h-tail W (4352) + sxu overlay
#define OFF_XA  22784   // 1024: x ping-pong 2 x 2 x 256
#define OFF_ADJ 23808   // 4352: adj+adjT (l0) | l>0: sxu overlay then h-tail W
#define DYNF    28160
#define DYNB    (DYNF*4)

// ---------------- device scratch ----------------
__device__ __align__(16) float g_hbuf[2][2048*64];
__device__ unsigned g_diag_key[LL*128];        // static zero-init; reset at run end
__device__ unsigned g_off_key [LL*128];
__device__ unsigned g_min_key4[LL] = {0xFFFFFFFFu,0xFFFFFFFFu,0xFFFFFFFFu,0xFFFFFFFFu};
__device__ int g_cnt, g_gen;

__device__ __forceinline__ unsigned fkey(float f) {
    unsigned u = __float_as_uint(f);
    return (u & 0x80000000u) ? ~u : (u | 0x80000000u);
}
__device__ __forceinline__ float funkey(unsigned k) {
    unsigned u = (k & 0x80000000u) ? (k & 0x7fffffffu) : ~k;
    return __uint_as_float(u);
}

// ---- software grid barrier ----
__device__ __forceinline__ void gsync() {
    __syncthreads();
    if (threadIdx.x == 0) {
        __threadfence();
        int g = *(volatile int*)&g_gen;
        if (atomicAdd(&g_cnt, 1) == GRID - 1) {
            g_cnt = 0;
            __threadfence();
            atomicExch(&g_gen, g + 1);
        } else {
            while (*(volatile int*)&g_gen == g) {}
        }
        __threadfence();
    }
    __syncthreads();
}

#define GBAR() asm volatile("bar.sync %0, %1;" :: "r"(barid), "r"(128) : "memory")

// ---------------- megakernel ----------------
__global__ void __launch_bounds__(TPB, 2)
mega(const int* ei, int E,
     const float* W0, const float* b0, const float* Ws, const float* bs,
     const float* ln_g, const float* ln_b,
     const float* fW0, const float* fb0, const float* fWs, const float* fbs,
     const float* fln_g, const float* fln_b,
     const float* opW, const float* opb, float* out)
{
    extern __shared__ __align__(16) float dyn[];
    __shared__ float slg[16], slb[16];
    __shared__ float sred[2][4][4], sred2[2][4][4];
    __shared__ float sfw0[64], sw0[64], sb0[64];
    __shared__ float psr[2];
    __shared__ int   sflag;

    int t   = threadIdx.x;
    int blk = blockIdx.x;
    int pair = blk >> 2;
    int b = pair >> 5, x = pair & 31;
    int y0 = (blk & 3) * 8;
    int ypar = t >> 7, tf = t & 127, wrp = tf >> 5, la = tf & 31;
    int barid = 1 + ypar;

    float* sadj  = dyn + OFF_ADJ;          // adj  (b,a,y)
    float* sadjT = dyn + OFF_ADJ + 2048;   // adjT (b,y,a)

    // ================= init: adjacency per block =================
    {
        if (t == 0) sflag = 0;
        __syncthreads();
        for (int i = t; i < 512; i += TPB)
            if (ei[2*i + 1] != 0) sflag = 1;     // int32 vs int64 detect
        for (int i = t; i < 2048; i += TPB) sadj[i] = 0.f;
        if (t < 64) { sw0[t] = W0[t]; sb0[t] = b0[t]; }
        __syncthreads();
        int stride = sflag ? 1 : 2;
        for (int e = t; e < E; e += TPB) {
            int e0 = ei[stride*e];
            int e1 = ei[stride*E + stride*e];
            int g  = e0 >> 5;
            int ls = e0 - (g << 5);
            int ld = e1 - (g << 5);
            if (g >= 0 && g < BB && ld >= 0 && ld < NN)
                atomicAdd(&sadj[(g << 10) + (ls << 5) + ld], 1.f);
        }
        __syncthreads();
        if (t < 64) { int bb = t >> 5, n = t & 31; sadj[(bb << 10) + n*33] = 2.f; }
        __syncthreads();
        for (int i = t; i < 2048; i += TPB) {
            int bb = i >> 10, aa = (i >> 5) & 31, yy = i & 31;
            sadjT[(bb << 10) + (yy << 5) + aa] = sadj[i];
        }
        if (tf < 4)
            dyn[OFF_XA + ypar*256 + tf*64] = sadj[(b << 10) + (x << 5) + y0 + 2*tf + ypar];
        __syncthreads();
    }

    // ================= layers =================
    for (int l = 0; l < LL; l++) {
        const float* hcur = g_hbuf[l & 1];
        float* bufA = dyn + OFF_SY + ypar*4352;
        float* bufB = bufA + 2176;
        float* ctw  = dyn + OFF_CT + (ypar*4 + wrp)*640;
        float* sxo  = dyn + OFF_XA + (l & 1)*512 + ypar*256;
        float* sxn  = dyn + OFF_XA + ((l + 1) & 1)*512 + ypar*256;
        // sxu overlay: l==0 -> free half of SY; l>0 -> own half of dead ADJ region
        float* sxup = (l == 0) ? (dyn + OFF_SY + 4352 + ypar*256)
                               : (dyn + OFF_ADJ + ypar*2176);
        int ffn_f = wrp*16 + (la >> 1);
        int half  = la & 1;

        // ---- staging ----
        if (l == 0) {
            for (int i = t; i < 4096; i += TPB)
                dyn[OFF_FW + (i >> 6)*140 + 68 + (i & 63)] = fW0[(i >> 6)*65 + 1 + (i & 63)];
            if (t < 64) sfw0[t] = fW0[t*65];
            // prefetch Ws[0] (h-tail) into first half of SY
            for (int i2 = t; i2 < 1024; i2 += TPB)
                __pipeline_memcpy_async(&dyn[OFF_SY + (i2 >> 4)*68 + (i2 & 15)*4],
                                        Ws + i2*4, 16);
            __pipeline_commit();
        } else {
            for (int i = t; i < 2048; i += TPB) {
                int f = i >> 5, u = i & 31;
                __pipeline_memcpy_async(&dyn[OFF_FW + f*140 + u*4 + (u >= 16 ? 4 : 0)],
                                        fWs + (l-1)*8192 + f*128 + u*4, 16);
            }
            const float* xb = hcur + ((b*32 + x)*32)*64;
            for (int v = tf; v < 512; v += 128)
                __pipeline_memcpy_async(&bufA[(v >> 4)*68 + (v & 15)*4], xb + v*4, 16);
            __pipeline_commit();
        }
        if (t < 16) { slg[t] = ln_g[l*16 + t]; slb[t] = ln_b[l*16 + t]; }
        float flg = fln_g[l*64 + ffn_f], flb = fln_b[l*64 + ffn_f];
        float fbias = (l == 0) ? fb0[ffn_f] : fbs[(l-1)*64 + ffn_f];
        if (l > 0) __pipeline_wait_prior(0);
        __syncthreads();

        // ---- x-side registers + folded q constants ----
        float hxr[16], gq[16];
        float A = 0.f, Bc = 0.f;
        {
            if (l == 0) {
                float adjx = sadj[(b << 10) + (x << 5) + la];
                #pragma unroll
                for (int d = 0; d < 16; d++)
                    hxr[d] = adjx*sw0[wrp*16 + d] + sb0[wrp*16 + d];
            } else {
                #pragma unroll
                for (int j = 0; j < 4; j++) {
                    float4 v = *(const float4*)&bufA[la*68 + wrp*16 + 4*j];
                    hxr[4*j] = v.x; hxr[4*j+1] = v.y; hxr[4*j+2] = v.z; hxr[4*j+3] = v.w;
                }
            }
            float s0 = 0.f, s1 = 0.f;
            #pragma unroll
            for (int d = 0; d < 16; d++) { s0 += hxr[d]; s1 += hxr[d]*hxr[d]; }
            float mn = s0 * (1.f/16.f);
            float rstd = rsqrtf(s1*(1.f/16.f) - mn*mn + EPSL);
            #pragma unroll
            for (int d = 0; d < 16; d++) {
                float qx = (hxr[d] - mn)*rstd*slg[d] + slb[d];
                gq[d] = qx * slg[d];
                A  += gq[d];
                Bc += qx * slb[d];
            }
        }

        const float* hyb = hcur + b*65536;
        if (l > 0) {   // prefetch iter-0 y-slab
            int y = y0 + ypar;
            for (int v = tf; v < 512; v += 128)
                __pipeline_memcpy_async(&bufB[(v >> 4)*68 + (v & 15)*4],
                                        hyb + (v >> 4)*2048 + y*64 + (v & 15)*4, 16);
            __pipeline_commit();
        }

        // ================= y-loop: attention + contraction only =================
        for (int i = 0; i < 4; i++) {
            int y = y0 + 2*i + ypar;

            float hyr[16];
            if (l == 0) {
                float adjy = sadjT[(b << 10) + (y << 5) + la];
                #pragma unroll
                for (int d = 0; d < 16; d++)
                    hyr[d] = adjy*sw0[wrp*16 + d] + sb0[wrp*16 + d];
            } else {
                __pipeline_wait_prior(0);
                GBAR();                        // slab ready; prior buffer free
                float* cur = (i & 1) ? bufA : bufB;
                #pragma unroll
                for (int j = 0; j < 4; j++) {
                    float4 v = *(const float4*)&cur[la*68 + wrp*16 + 4*j];
                    hyr[4*j] = v.x; hyr[4*j+1] = v.y; hyr[4*j+2] = v.z; hyr[4*j+3] = v.w;
                }
                if (i < 3) {
                    float* nxt = (i & 1) ? bufB : bufA;
                    int yn = y + 2;
                    for (int v = tf; v < 512; v += 128)
                        __pipeline_memcpy_async(&nxt[(v >> 4)*68 + (v & 15)*4],
                                                hyb + (v >> 4)*2048 + yn*64 + (v & 15)*4, 16);
                    __pipeline_commit();
                }
            }

            // stats
            float s0 = 0.f, s1 = 0.f, dg = 0.f, mprod = 0.f, eprod = 0.f;
            #pragma unroll
            for (int d = 0; d < 16; d++) {
                s0 += hyr[d];
                s1 += hyr[d]*hyr[d];
                dg += gq[d]*hyr[d];
                float pr = hxr[d]*hyr[d];
                mprod += pr;
                eprod += pr*pr;
            }
            float mny = s0 * (1.f/16.f);
            float rsy = rsqrtf(s1*(1.f/16.f) - mny*mny + EPSL);
            float s = (rsy*(dg - mny*A) + Bc) * 0.25f;
            float mm = mprod * (1.f/16.f);
            float rstd = rsqrtf(eprod*(1.f/16.f) - mm*mm + EPSL);

            // softmax over a = warp lanes (LN-bounded scores)
            float ex = __expf(s);
            float t2 = ex, t3 = ex * mm * rstd;
            #pragma unroll
            for (int o = 16; o > 0; o >>= 1) {
                t2 += __shfl_xor_sync(~0u, t2, o);
                t3 += __shfl_xor_sync(~0u, t3, o);
            }
            float inv = 1.f / t2;
            float watt = ex * rstd * inv;
            float wcs  = t3 * inv;

            // contraction: warp-private smem transpose -> sxup[i*64 + ...]
            #pragma unroll
            for (int j = 0; j < 4; j++) {
                float4 v;
                v.x = watt*hxr[4*j  ]*hyr[4*j  ];
                v.y = watt*hxr[4*j+1]*hyr[4*j+1];
                v.z = watt*hxr[4*j+2]*hyr[4*j+2];
                v.w = watt*hxr[4*j+3]*hyr[4*j+3];
                *(float4*)&ctw[la*20 + 4*j] = v;
            }
            __syncwarp();
            {
                int dd = la & 15, hh = la >> 4;
                float a0 = 0.f, a1 = 0.f, a2 = 0.f, a3 = 0.f;
                #pragma unroll
                for (int aa = 0; aa < 4; aa++) {
                    a0 += ctw[((aa     )*2 + hh)*20 + dd];
                    a1 += ctw[((aa +  4)*2 + hh)*20 + dd];
                    a2 += ctw[((aa +  8)*2 + hh)*20 + dd];
                    a3 += ctw[((aa + 12)*2 + hh)*20 + dd];
                }
                float acc = (a0 + a1) + (a2 + a3);
                acc += __shfl_xor_sync(~0u, acc, 16);
                if (la < 16)
                    sxup[i*64 + wrp*16 + la] = slg[la]*(acc - wcs) + slb[la];
            }
            __syncwarp();                      // ctw safe for next iter
        } // y loop

        GBAR();                                // all sxup[*] visible to group

        // ================= batched FFN over 4 cells =================
        float acc0, acc1, acc2, acc3;
        if (l == 0 && half == 0) {
            float w0f = sfw0[ffn_f];
            acc0 = fbias + w0f*sxo[0];
            acc1 = fbias + w0f*sxo[64];
            acc2 = fbias + w0f*sxo[128];
            acc3 = fbias + w0f*sxo[192];
        } else {
            const float4* fw = (const float4*)&dyn[OFF_FW + ffn_f*140 + (half ? 68 : 0)];
            float base = half ? 0.f : fbias;
            acc0 = base; acc1 = base; acc2 = base; acc3 = base;
            const float4* x0 = (const float4*)(half ? (sxup)       : (sxo));
            const float4* x1 = (const float4*)(half ? (sxup + 64)  : (sxo + 64));
            const float4* x2 = (const float4*)(half ? (sxup + 128) : (sxo + 128));
            const float4* x3 = (const float4*)(half ? (sxup + 192) : (sxo + 192));
            #pragma unroll
            for (int j = 0; j < 16; j++) {
                float4 w = fw[j];
                float4 v0 = x0[j], v1 = x1[j], v2 = x2[j], v3 = x3[j];
                acc0 += w.x*v0.x + w.y*v0.y + w.z*v0.z + w.w*v0.w;
                acc1 += w.x*v1.x + w.y*v1.y + w.z*v1.z + w.w*v1.w;
                acc2 += w.x*v2.x + w.y*v2.y + w.z*v2.z + w.w*v2.w;
                acc3 += w.x*v3.x + w.y*v3.y + w.z*v3.z + w.w*v3.w;
            }
        }
        acc0 += __shfl_xor_sync(~0u, acc0, 1);
        acc1 += __shfl_xor_sync(~0u, acc1, 1);
        acc2 += __shfl_xor_sync(~0u, acc2, 1);
        acc3 += __shfl_xor_sync(~0u, acc3, 1);

        // LN trees for 4 cells (8 values, one pipelined pass)
        {
            float u0 = acc0, u1 = acc1, u2 = acc2, u3 = acc3;
            float q0 = acc0*acc0, q1 = acc1*acc1, q2 = acc2*acc2, q3 = acc3*acc3;
            #pragma unroll
            for (int o = 16; o > 0; o >>= 1) {
                u0 += __shfl_xor_sync(~0u, u0, o);
                u1 += __shfl_xor_sync(~0u, u1, o);
                u2 += __shfl_xor_sync(~0u, u2, o);
                u3 += __shfl_xor_sync(~0u, u3, o);
                q0 += __shfl_xor_sync(~0u, q0, o);
                q1 += __shfl_xor_sync(~0u, q1, o);
                q2 += __shfl_xor_sync(~0u, q2, o);
                q3 += __shfl_xor_sync(~0u, q3, o);
            }
            if (la == 0) {
                sred [ypar][0][wrp] = u0; sred [ypar][1][wrp] = u1;
                sred [ypar][2][wrp] = u2; sred [ypar][3][wrp] = u3;
                sred2[ypar][0][wrp] = q0; sred2[ypar][1][wrp] = q1;
                sred2[ypar][2][wrp] = q2; sred2[ypar][3][wrp] = q3;
            }
        }
        GBAR();

        // ---- epilogue: LN + write sxn + pooling, per cell ----
        float offm = -3.0e38f, minv = 3.0e38f, dval = -3.0e38f;
        bool sawdiag = false;
        float accs[4] = {acc0, acc1, acc2, acc3};
        #pragma unroll
        for (int c = 0; c < 4; c++) {
            float mean = (sred[ypar][c][0] + sred[ypar][c][1] +
                          sred[ypar][c][2] + sred[ypar][c][3]) * (1.f/128.f);
            float ms   = (sred2[ypar][c][0] + sred2[ypar][c][1] +
                          sred2[ypar][c][2] + sred2[ypar][c][3]) * (1.f/128.f);
            float xn = (accs[c] - mean)*rsqrtf(ms - mean*mean + EPSL)*flg + flb;
            int y = y0 + 2*c + ypar;
            if (half == 0) {
                sxn[c*64 + ffn_f] = xn;
                minv = fminf(minv, xn);
                if (y == x) { dval = xn; sawdiag = true; }
                else offm = fmaxf(offm, xn);
            }
        }

        // ---- pooling atomics ----
        if (half == 0) {
            atomicMax(&g_off_key[l*128 + b*64 + ffn_f], fkey(offm));
            if (sawdiag) atomicMax(&g_diag_key[l*128 + b*64 + ffn_f], fkey(dval));
        }
        {
            float w = minv;
            #pragma unroll
            for (int o = 16; o > 0; o >>= 1) w = fminf(w, __shfl_xor_sync(~0u, w, o));
            if (la == 0) atomicMin(&g_min_key4[l], fkey(w));
        }

        // ---- prefetch h-tail W (l>=1) into ADJ region (own half per group) ----
        if (l >= 1 && l < LL - 1) {
            for (int v = tf; v < 512; v += 128) {
                int f = ypar*32 + (v >> 4), u = v & 15;
                __pipeline_memcpy_async(&dyn[OFF_ADJ + f*68 + u*4],
                                        Ws + l*4096 + f*64 + u*4, 16);
            }
            __pipeline_commit();
        }

        // ---- h-tail: next-layer h for own 8 cells ----
        if (l < LL - 1) {
            __pipeline_wait_prior(0);
            __syncthreads();
            const float* wbase = (l == 0) ? (dyn + OFF_SY) : (dyn + OFF_ADJ);
            int f = t & 63, yyA = t >> 6, yyB = yyA + 4;
            const float4* wrow = (const float4*)&wbase[f*68];
            const float4* xA = (const float4*)&dyn[OFF_XA + ((l+1)&1)*512 + (yyA & 1)*256 + (yyA >> 1)*64];
            const float4* xB = (const float4*)&dyn[OFF_XA + ((l+1)&1)*512 + (yyB & 1)*256 + (yyB >> 1)*64];
            float accA = bs[l*64 + f], accB = accA;
            #pragma unroll
            for (int j = 0; j < 16; j++) {
                float4 w = wrow[j], va = xA[j], vb = xB[j];
                accA += w.x*va.x + w.y*va.y + w.z*va.z + w.w*va.w;
                accB += w.x*vb.x + w.y*vb.y + w.z*vb.z + w.w*vb.w;
            }
            float* hn = g_hbuf[(l+1) & 1];
            hn[((b*32 + x)*32 + y0 + yyA)*64 + f] = accA;
            hn[((b*32 + x)*32 + y0 + yyB)*64 + f] = accB;
        }
        gsync();
    } // layers

    // ================= final: pool_finish all layers + BN (block 0) =================
    if (blk == 0) {
        float* pooled4 = dyn + OFF_CT;         // 4 x 256
        float* psum    = dyn + OFF_FW;         // 256
        for (int l2 = 0; l2 < LL; l2++) {
            float d0 = 0.f, d1 = 0.f, o0 = 0.f, o1 = 0.f, gmin = 0.f;
            if (t < 64) {
                d0 = funkey(g_diag_key[l2*128 + t]);
                d1 = funkey(g_diag_key[l2*128 + 64 + t]);
                o0 = funkey(g_off_key [l2*128 + t]);
                o1 = funkey(g_off_key [l2*128 + 64 + t]);
                gmin = funkey(g_min_key4[l2]);
                float m = fmaxf(d0, d1);
                #pragma unroll
                for (int o = 16; o > 0; o >>= 1) m = fmaxf(m, __shfl_xor_sync(~0u, m, o));
                if ((t & 31) == 0) psr[t >> 5] = m;
            }
            __syncthreads();
            if (t < 64) {
                float gdm = fmaxf(psr[0], psr[1]);
                float val = fabsf(gdm - gmin);
                pooled4[l2*256 + t]       = d0;
                pooled4[l2*256 + 64 + t]  = fmaxf(o0, d0 - val);
                pooled4[l2*256 + 128 + t] = d1;
                pooled4[l2*256 + 192 + t] = fmaxf(o1, d1 - val);
            }
            __syncthreads();
        }
        {
            int l2 = t >> 6, bq = (t >> 5) & 1, j = t & 31;
            const float4* w4 = (const float4*)(opW + l2*4096 + j*128);
            const float4* p4 = (const float4*)&pooled4[l2*256 + bq*128];
            float acc = opb[l2*32 + j];
            #pragma unroll
            for (int k = 0; k < 32; k++) {
                float4 w = w4[k], p = p4[k];
                acc += w.x*p.x + w.y*p.y + w.z*p.z + w.w*p.w;
            }
            psum[t] = acc;
        }
        __syncthreads();
        if (t < 32) {
            float s0 = psum[t]      + psum[64 + t] + psum[128 + t] + psum[192 + t];
            float s1 = psum[32 + t] + psum[96 + t] + psum[160 + t] + psum[224 + t];
            float m = 0.5f*(s0 + s1);
            float v = 0.5f*((s0 - m)*(s0 - m) + (s1 - m)*(s1 - m));
            float r = rsqrtf(v + EPSL);
            out[t]      = (s0 - m)*r;
            out[32 + t] = (s1 - m)*r;
        }
        // reset keys for next graph replay
        __syncthreads();
        for (int i = t; i < LL*128; i += TPB) { g_diag_key[i] = 0u; g_off_key[i] = 0u; }
        if (t < LL) g_min_key4[t] = 0xFFFFFFFFu;
    }
}

// ---------------- launch ----------------
extern "C" void kernel_launch(void* const* d_in, const int* in_sizes, int n_in,
                              void* d_out, int out_size) {
    const int*   ei    = (const int*)  d_in[0];
    const float* W0    = (const float*)d_in[2];
    const float* b0    = (const float*)d_in[3];
    const float* Ws    = (const float*)d_in[4];
    const float* bs    = (const float*)d_in[5];
    const float* ln_g  = (const float*)d_in[6];
    const float* ln_b  = (const float*)d_in[7];
    const float* fW0   = (const float*)d_in[8];
    const float* fb0   = (const float*)d_in[9];
    const float* fWs   = (const float*)d_in[10];
    const float* fbs   = (const float*)d_in[11];
    const float* fln_g = (const float*)d_in[12];
    const float* fln_b = (const float*)d_in[13];
    const float* opW   = (const float*)d_in[14];
    const float* opb   = (const float*)d_in[15];
    int E = in_sizes[0] / 2;

    cudaFuncSetAttribute(mega, cudaFuncAttributeMaxDynamicSharedMemorySize, DYNB);
    mega<<<GRID, TPB, DYNB>>>(ei, E, W0, b0, Ws, bs, ln_g, ln_b,
                              fW0, fb0, fWs, fbs, fln_g, fln_b,
                              opW, opb, (float*)d_out);
}